// round 14
// baseline (speedup 1.0000x reference)
#include <cuda_runtime.h>
#include <cuda_fp16.h>
#include <stdint.h>
#include <math.h>

// ---------------- problem constants ----------------
#define B_   2
#define T_   1024
#define E_   1024
#define H_   16
#define HD_  64
#define L_   8
#define FF_  4096
#define V_   32000
#define BT_  (B_ * T_)
#define EPS_ 1e-5f
#define SCALE_ 0.03125f   // 1/sqrt(E)

typedef __half hp16;

__device__ __forceinline__ hp16 f2h(float x) { return __float2half_rn(x); }
__device__ __forceinline__ float h2f(hp16 x) { return __half2float(x); }
__device__ __forceinline__ unsigned short h2us(hp16 x) { return __half_as_ushort(x); }

// ---------------- scratch (device globals) ----------------
__device__ float g_x[BT_ * E_];
__device__ float g_scores[(size_t)B_ * H_ * T_ * T_];
__device__ float g_logits[(size_t)BT_ * V_];
__device__ float g_rowloss[BT_];
__device__ float g_lossdummy[4];
__device__ hp16 g_hhi[BT_ * E_];
__device__ hp16 g_hlo[BT_ * E_];
__device__ hp16 g_qkvhi[BT_ * 3 * E_];
__device__ hp16 g_qkvlo[BT_ * 3 * E_];
__device__ hp16 g_vthi[(size_t)B_ * H_ * HD_ * T_];
__device__ hp16 g_vtlo[(size_t)B_ * H_ * HD_ * T_];
__device__ hp16 g_phi[(size_t)B_ * H_ * T_ * T_];
__device__ hp16 g_plo[(size_t)B_ * H_ * T_ * T_];
__device__ hp16 g_ffhi[(size_t)BT_ * FF_];
__device__ hp16 g_fflo[(size_t)BT_ * FF_];
__device__ hp16 g_ohi[BT_ * E_];
__device__ hp16 g_olo[BT_ * E_];
__device__ hp16 g_wthi[(size_t)V_ * E_];
__device__ hp16 g_wtlo[(size_t)V_ * E_];

// ---------------- reductions (blockDim.x == 256) ----------------
__device__ __forceinline__ float blockSum256(float v) {
    __shared__ float sh[8];
    int tid = threadIdx.x;
    #pragma unroll
    for (int o = 16; o; o >>= 1) v += __shfl_xor_sync(0xffffffffu, v, o);
    __syncthreads();
    if ((tid & 31) == 0) sh[tid >> 5] = v;
    __syncthreads();
    v = sh[tid & 7];
    #pragma unroll
    for (int o = 4; o; o >>= 1) v += __shfl_xor_sync(0xffffffffu, v, o);
    return v;
}

__device__ __forceinline__ float blockMax256(float v) {
    __shared__ float sh[8];
    int tid = threadIdx.x;
    #pragma unroll
    for (int o = 16; o; o >>= 1) v = fmaxf(v, __shfl_xor_sync(0xffffffffu, v, o));
    __syncthreads();
    if ((tid & 31) == 0) sh[tid >> 5] = v;
    __syncthreads();
    v = sh[tid & 7];
    #pragma unroll
    for (int o = 4; o; o >>= 1) v = fmaxf(v, __shfl_xor_sync(0xffffffffu, v, o));
    return v;
}

// ---------------- embedding ----------------
__global__ void embed_kernel(const int* __restrict__ ctx,
                             const float* __restrict__ tok,
                             const float* __restrict__ pos) {
    int gid = blockIdx.x * blockDim.x + threadIdx.x;
    int bt = gid >> 10;
    int e  = gid & (E_ - 1);
    int t  = bt & (T_ - 1);
    g_x[gid] = tok[(size_t)ctx[bt] * E_ + e] + pos[t * E_ + e];
}

// ---------------- layernorm -> split fp16 hi/lo planes ----------------
__global__ void ln_split_kernel(const float* __restrict__ in,
                                hp16* __restrict__ hhi, hp16* __restrict__ hlo,
                                const float* __restrict__ g, const float* __restrict__ b) {
    int row = blockIdx.x;
    int tid = threadIdx.x;
    const float4* rp = (const float4*)(in + (size_t)row * E_);
    float4 v = rp[tid];
    float s  = v.x + v.y + v.z + v.w;
    float ss = v.x * v.x + v.y * v.y + v.z * v.z + v.w * v.w;
    s  = blockSum256(s);
    __syncthreads();
    ss = blockSum256(ss);
    float mean = s * (1.0f / E_);
    float var  = ss * (1.0f / E_) - mean * mean;
    float inv  = rsqrtf(var + EPS_);
    int e = tid * 4;
    float o[4];
    o[0] = (v.x - mean) * inv * g[e + 0] + b[e + 0];
    o[1] = (v.y - mean) * inv * g[e + 1] + b[e + 1];
    o[2] = (v.z - mean) * inv * g[e + 2] + b[e + 2];
    o[3] = (v.w - mean) * inv * g[e + 3] + b[e + 3];
    ushort4 ho, lw;
    unsigned short* hpp = &ho.x;
    unsigned short* lpp = &lw.x;
    #pragma unroll
    for (int j = 0; j < 4; j++) {
        hp16 h = f2h(o[j]);
        hp16 l = f2h(o[j] - h2f(h));
        hpp[j] = h2us(h);
        lpp[j] = h2us(l);
    }
    ((ushort4*)(hhi + (size_t)row * E_))[tid] = ho;
    ((ushort4*)(hlo + (size_t)row * E_))[tid] = lw;
}

// ---------------- weight transpose+split ----------------
__global__ void wt_tsplit(const float* __restrict__ W,
                          hp16* __restrict__ Thi, hp16* __restrict__ Tlo,
                          int N, int K) {
    __shared__ float s[32][33];
    int n0 = blockIdx.x * 32;
    int k0 = blockIdx.y * 32;
    int tx = threadIdx.x;   // 0..7
    int ty = threadIdx.y;   // 0..31
    float4 rv = *(const float4*)(W + (size_t)(k0 + ty) * N + n0 + tx * 4);
    s[ty][tx * 4 + 0] = rv.x;
    s[ty][tx * 4 + 1] = rv.y;
    s[ty][tx * 4 + 2] = rv.z;
    s[ty][tx * 4 + 3] = rv.w;
    __syncthreads();
    ushort4 ho, lw;
    unsigned short* hpp = &ho.x;
    unsigned short* lpp = &lw.x;
    #pragma unroll
    for (int j = 0; j < 4; j++) {
        float f = s[tx * 4 + j][ty];
        hp16 h = f2h(f);
        hp16 l = f2h(f - h2f(h));
        hpp[j] = h2us(h);
        lpp[j] = h2us(l);
    }
    size_t off = (size_t)(n0 + ty) * K + k0 + tx * 4;
    *(ushort4*)(Thi + off) = ho;
    *(ushort4*)(Tlo + off) = lw;
}

// ---------------- V transpose per head ----------------
__global__ void vt_tsplit_kernel() {
    __shared__ hp16 sh[32][33];
    __shared__ hp16 sl[32][33];
    int z = blockIdx.z;  int b = z >> 4;  int h = z & 15;
    int t0 = blockIdx.x * 32, d0 = blockIdx.y * 32;
    int tx = threadIdx.x, ty = threadIdx.y;
    size_t src = (size_t)(b * T_ + t0 + ty) * (3 * E_) + 2 * E_ + h * HD_ + d0 + tx;
    sh[ty][tx] = g_qkvhi[src];
    sl[ty][tx] = g_qkvlo[src];
    __syncthreads();
    size_t dst = (size_t)(z * HD_ + d0 + ty) * T_ + t0 + tx;
    g_vthi[dst] = sh[tx][ty];
    g_vtlo[dst] = sl[tx][ty];
}

// ============ MMA helpers (fp16 inputs, fp32 accumulate) ============
#define MMA16816(c, a, b) \
  asm volatile("mma.sync.aligned.m16n8k16.row.col.f32.f16.f16.f32 " \
    "{%0,%1,%2,%3}, {%4,%5,%6,%7}, {%8,%9}, {%0,%1,%2,%3};" \
    : "+f"((c)[0]), "+f"((c)[1]), "+f"((c)[2]), "+f"((c)[3]) \
    : "r"((a)[0]), "r"((a)[1]), "r"((a)[2]), "r"((a)[3]), \
      "r"((b)[0]), "r"((b)[1]))

#define CP16(dst_u32, src) \
  asm volatile("cp.async.cg.shared.global [%0], [%1], 16;" :: "r"(dst_u32), "l"(src))

__device__ __forceinline__ void ldsm4(uint32_t* r, unsigned a) {
    asm volatile("ldmatrix.sync.aligned.m8n8.x4.shared.b16 {%0,%1,%2,%3}, [%4];"
        : "=r"(r[0]), "=r"(r[1]), "=r"(r[2]), "=r"(r[3]) : "r"(a));
}

#define SM_STAGE 20480
#define SM_MAT   5120
#define SM_ROW   40
#define SM_STAGE_B 40960u
#define SM_MAT_B   10240u
#define SM_TILE_B  1280u

// gemm-specific: 3 planes (Ahi, Bhi, Blo) per stage
#define G_STAGE_B  30720u

// ============ fp16 2-term GEMM: C = Ahi @ (Bhi+Blo)^T, 128x128x32, 3-stage ============
__global__ void __launch_bounds__(256, 1) mma_gemm(
        const hp16* __restrict__ Ahi, const hp16* __restrict__ Alo, int lda,
        const hp16* __restrict__ Bthi, const hp16* __restrict__ Btlo, int ldb,
        const float* __restrict__ bias, const float* __restrict__ res,
        float* __restrict__ C, hp16* __restrict__ Chi, hp16* __restrict__ Clo,
        int ldc, int K, int doRelu) {
    extern __shared__ hp16 smem[];

    int tid  = threadIdx.x;
    int warp = tid >> 5, lane = tid & 31;
    int wm = warp & 3;
    int wn = warp >> 2;
    int g  = lane >> 2;
    int tg = lane & 3;
    int t  = lane >> 3, rr = lane & 7;

    int row0 = blockIdx.y * 128;
    int col0 = blockIdx.x * 128;

    unsigned smem_u32 = (unsigned)__cvta_generic_to_shared(smem);
    unsigned aoffB = 2u * ((wm * 32 + (t & 1) * 8 + rr) * SM_ROW + (t >> 1) * 8);
    unsigned boffB = 2u * ((wn * 64 + (t >> 1) * 8 + rr) * SM_ROW + (t & 1) * 8);

    float acc[2][8][4];
    #pragma unroll
    for (int i = 0; i < 2; i++)
        #pragma unroll
        for (int j = 0; j < 8; j++)
            #pragma unroll
            for (int r = 0; r < 4; r++) acc[i][j][r] = 0.0f;

    int nk = K >> 5;

    auto load_stage = [&](int stage, int k0) {
        #pragma unroll
        for (int i = 0; i < 6; i++) {
            int idx = i * 256 + tid;        // 1536 chunks: plane(3) x row(128) x kc(4)
            int plane = idx >> 9;
            int rem = idx & 511;
            int row = rem >> 2;
            int kc  = rem & 3;
            unsigned dst = smem_u32 + (unsigned)stage * G_STAGE_B +
                (unsigned)plane * SM_MAT_B + 2u * (row * SM_ROW + kc * 8);
            const hp16* P = (plane == 0) ? Ahi : (plane == 1) ? Bthi : Btlo;
            int base_row = (plane == 0) ? row0 : col0;
            int ld = (plane == 0) ? lda : ldb;
            CP16(dst, P + (size_t)(base_row + row) * ld + k0 + kc * 8);
        }
        asm volatile("cp.async.commit_group;");
    };

    load_stage(0, 0);
    if (nk > 1) load_stage(1, 32);

    for (int kt = 0; kt < nk; kt++) {
        if (kt + 1 < nk) { asm volatile("cp.async.wait_group 1;"); }
        else             { asm volatile("cp.async.wait_group 0;"); }
        __syncthreads();

        unsigned sb  = smem_u32 + (unsigned)(kt % 3) * G_STAGE_B;
        unsigned aHi = sb + aoffB;
        unsigned bHi = sb + SM_MAT_B + boffB;
        unsigned bLo = bHi + SM_MAT_B;

        #pragma unroll
        for (int kk = 0; kk < 32; kk += 16) {
            uint32_t ah[2][4];
            ldsm4(ah[0], aHi + 2 * kk);
            ldsm4(ah[1], aHi + SM_TILE_B + 2 * kk);
            uint32_t bh[4][4], bl[4][4];
            #pragma unroll
            for (int p = 0; p < 4; p++) {
                ldsm4(bh[p], bHi + p * SM_TILE_B + 2 * kk);
                ldsm4(bl[p], bLo + p * SM_TILE_B + 2 * kk);
            }
            // term hh: 16 independent MMAs
            #pragma unroll
            for (int p = 0; p < 4; p++)
                #pragma unroll
                for (int mi = 0; mi < 2; mi++) {
                    MMA16816(acc[mi][2 * p],     ah[mi], &bh[p][0]);
                    MMA16816(acc[mi][2 * p + 1], ah[mi], &bh[p][2]);
                }
            // term hl
            #pragma unroll
            for (int p = 0; p < 4; p++)
                #pragma unroll
                for (int mi = 0; mi < 2; mi++) {
                    MMA16816(acc[mi][2 * p],     ah[mi], &bl[p][0]);
                    MMA16816(acc[mi][2 * p + 1], ah[mi], &bl[p][2]);
                }
        }
        __syncthreads();
        if (kt + 2 < nk) load_stage((kt + 2) % 3, (kt + 2) << 5);
    }

    // ---- epilogue ----
    #pragma unroll
    for (int mi = 0; mi < 2; mi++) {
        int r = row0 + wm * 32 + mi * 16 + g;
        #pragma unroll
        for (int ni = 0; ni < 8; ni++) {
            int c = col0 + wn * 64 + ni * 8 + tg * 2;
            float v0 = acc[mi][ni][0], v1 = acc[mi][ni][1];
            float v2 = acc[mi][ni][2], v3 = acc[mi][ni][3];
            if (bias) {
                float b0 = bias[c], b1 = bias[c + 1];
                v0 += b0; v1 += b1; v2 += b0; v3 += b1;
            }
            if (doRelu) {
                v0 = fmaxf(v0, 0.0f); v1 = fmaxf(v1, 0.0f);
                v2 = fmaxf(v2, 0.0f); v3 = fmaxf(v3, 0.0f);
            }
            if (Chi) {
                float vv[4] = {v0, v1, v2, v3};
                hp16 hh[4], ll[4];
                #pragma unroll
                for (int j = 0; j < 4; j++) {
                    hh[j] = f2h(vv[j]);
                    ll[j] = f2h(vv[j] - h2f(hh[j]));
                }
                *(uint32_t*)(Chi + (size_t)r * ldc + c)       = *(uint32_t*)&hh[0];
                *(uint32_t*)(Chi + (size_t)(r + 8) * ldc + c) = *(uint32_t*)&hh[2];
                *(uint32_t*)(Clo + (size_t)r * ldc + c)       = *(uint32_t*)&ll[0];
                *(uint32_t*)(Clo + (size_t)(r + 8) * ldc + c) = *(uint32_t*)&ll[2];
            } else {
                if (res) {
                    v0 += res[(size_t)r * ldc + c];
                    v1 += res[(size_t)r * ldc + c + 1];
                    v2 += res[(size_t)(r + 8) * ldc + c];
                    v3 += res[(size_t)(r + 8) * ldc + c + 1];
                }
                *(float2*)(C + (size_t)r * ldc + c)       = make_float2(v0, v1);
                *(float2*)(C + (size_t)(r + 8) * ldc + c) = make_float2(v2, v3);
            }
        }
    }
}

// ============ attention scores: S = scale * Q @ K^T (3-term, term-major) ============
__global__ void __launch_bounds__(256, 1) attn_scores_mma() {
    extern __shared__ hp16 smem[];
    int z = blockIdx.z;
    int qt = blockIdx.y, kt = blockIdx.x;
    if (kt > qt) return;
    int b = z >> 4, h = z & 15;

    const hp16* Ahi = g_qkvhi + (size_t)b * T_ * 3 * E_ + h * HD_;
    const hp16* Alo = g_qkvlo + (size_t)b * T_ * 3 * E_ + h * HD_;
    const hp16* Bhi = g_qkvhi + (size_t)b * T_ * 3 * E_ + E_ + h * HD_;
    const hp16* Blo = g_qkvlo + (size_t)b * T_ * 3 * E_ + E_ + h * HD_;
    const int ld = 3 * E_;
    float* C = g_scores + (size_t)z * T_ * T_;

    int tid  = threadIdx.x;
    int warp = tid >> 5, lane = tid & 31;
    int wm = warp & 3, wn = warp >> 2;
    int g = lane >> 2, tg = lane & 3;
    int t = lane >> 3, rr = lane & 7;
    int row0 = qt * 128, col0 = kt * 128;

    const hp16* planes[4] = {Ahi, Alo, Bhi, Blo};
    unsigned smem_u32 = (unsigned)__cvta_generic_to_shared(smem);
    unsigned aoffB = 2u * ((wm * 32 + (t & 1) * 8 + rr) * SM_ROW + (t >> 1) * 8);
    unsigned boffB = 2u * ((wn * 64 + (t >> 1) * 8 + rr) * SM_ROW + (t & 1) * 8);

    float acc[2][8][4];
    #pragma unroll
    for (int i = 0; i < 2; i++)
        #pragma unroll
        for (int j = 0; j < 8; j++)
            #pragma unroll
            for (int r = 0; r < 4; r++) acc[i][j][r] = 0.0f;

    auto load_stage = [&](int stage, int k0) {
        #pragma unroll
        for (int m = 0; m < 4; m++) {
            const hp16* P = planes[m];
            int base_row = (m < 2) ? row0 : col0;
            #pragma unroll
            for (int rep = 0; rep < 2; rep++) {
                int chunk = rep * 256 + tid;
                int row = chunk >> 2;
                int kc  = chunk & 3;
                unsigned dst = smem_u32 +
                    2u * (stage * SM_STAGE + m * SM_MAT + row * SM_ROW + kc * 8);
                CP16(dst, P + (size_t)(base_row + row) * ld + k0 + kc * 8);
            }
        }
        asm volatile("cp.async.commit_group;");
    };

    load_stage(0, 0);

    #pragma unroll
    for (int kt2 = 0; kt2 < 2; kt2++) {
        if (kt2 == 0) {
            load_stage(1, 32);
            asm volatile("cp.async.wait_group 1;");
        } else {
            asm volatile("cp.async.wait_group 0;");
        }
        __syncthreads();

        unsigned sb  = smem_u32 + (unsigned)kt2 * SM_STAGE_B;
        unsigned aHi = sb + aoffB;
        unsigned aLo = aHi + SM_MAT_B;
        unsigned bHi = sb + 2u * SM_MAT_B + boffB;
        unsigned bLo = bHi + SM_MAT_B;

        #pragma unroll
        for (int kk = 0; kk < 32; kk += 16) {
            uint32_t ah[2][4], al[2][4];
            ldsm4(ah[0], aHi + 2 * kk);
            ldsm4(ah[1], aHi + SM_TILE_B + 2 * kk);
            ldsm4(al[0], aLo + 2 * kk);
            ldsm4(al[1], aLo + SM_TILE_B + 2 * kk);
            uint32_t bh[4][4], bl[4][4];
            #pragma unroll
            for (int p = 0; p < 4; p++) {
                ldsm4(bh[p], bHi + p * SM_TILE_B + 2 * kk);
                ldsm4(bl[p], bLo + p * SM_TILE_B + 2 * kk);
            }
            #pragma unroll
            for (int p = 0; p < 4; p++)
                #pragma unroll
                for (int mi = 0; mi < 2; mi++) {
                    MMA16816(acc[mi][2 * p],     ah[mi], &bh[p][0]);
                    MMA16816(acc[mi][2 * p + 1], ah[mi], &bh[p][2]);
                }
            #pragma unroll
            for (int p = 0; p < 4; p++)
                #pragma unroll
                for (int mi = 0; mi < 2; mi++) {
                    MMA16816(acc[mi][2 * p],     ah[mi], &bl[p][0]);
                    MMA16816(acc[mi][2 * p + 1], ah[mi], &bl[p][2]);
                }
            #pragma unroll
            for (int p = 0; p < 4; p++)
                #pragma unroll
                for (int mi = 0; mi < 2; mi++) {
                    MMA16816(acc[mi][2 * p],     al[mi], &bh[p][0]);
                    MMA16816(acc[mi][2 * p + 1], al[mi], &bh[p][2]);
                }
        }
        __syncthreads();
    }

    #pragma unroll
    for (int mi = 0; mi < 2; mi++) {
        int r = row0 + wm * 32 + mi * 16 + g;
        #pragma unroll
        for (int ni = 0; ni < 8; ni++) {
            int c = col0 + wn * 64 + ni * 8 + tg * 2;
            *(float2*)(C + (size_t)r * T_ + c) =
                make_float2(acc[mi][ni][0] * SCALE_, acc[mi][ni][1] * SCALE_);
            *(float2*)(C + (size_t)(r + 8) * T_ + c) =
                make_float2(acc[mi][ni][2] * SCALE_, acc[mi][ni][3] * SCALE_);
        }
    }
}

// ---------------- causal row softmax -> split fp16 P planes ----------------
__global__ void softmax_split_kernel() {
    int idx = blockIdx.x;
    int q = idx & (T_ - 1);
    const float* row = g_scores + (size_t)idx * T_;
    hp16* ph = g_phi + (size_t)idx * T_;
    hp16* pl = g_plo + (size_t)idx * T_;
    int n = q + 1;
    int kmax = ((q >> 7) + 1) << 7;
    int tid = threadIdx.x;
    float m = -1e30f;
    for (int i = tid; i < n; i += 256) m = fmaxf(m, row[i]);
    m = blockMax256(m);
    __syncthreads();
    float s = 0.0f;
    for (int i = tid; i < n; i += 256) s += __expf(row[i] - m);
    s = blockSum256(s);
    float inv = 1.0f / s;
    for (int i = tid; i < n; i += 256) {
        float p = __expf(row[i] - m) * inv;
        hp16 h = f2h(p);
        ph[i] = h;
        pl[i] = f2h(p - h2f(h));
    }
    hp16 z16 = f2h(0.0f);
    for (int i = n + tid; i < kmax; i += 256) { ph[i] = z16; pl[i] = z16; }
}

// ============ AV: O = P @ V, 128x64 tile, causal K bound (3-term) ============
#define AV_A_PLANE 5120
#define AV_B_PLANE 2560
#define AV_STAGE   15360
#define AV_STAGE_B 30720u

__global__ void __launch_bounds__(256, 1) attn_av_mma() {
    extern __shared__ hp16 smem[];
    int z = blockIdx.z;
    int qt = blockIdx.y;
    int b = z >> 4, h = z & 15;
    int row0 = qt * 128;

    const hp16* Ahi = g_phi + (size_t)z * T_ * T_;
    const hp16* Alo = g_plo + (size_t)z * T_ * T_;
    const hp16* Bhi = g_vthi + (size_t)z * HD_ * T_;
    const hp16* Blo = g_vtlo + (size_t)z * HD_ * T_;

    int tid  = threadIdx.x;
    int warp = tid >> 5, lane = tid & 31;
    int g = lane >> 2, tg = lane & 3;
    int t = lane >> 3, rr = lane & 7;
    unsigned smem_u32 = (unsigned)__cvta_generic_to_shared(smem);
    unsigned aoffB = 2u * ((warp * 16 + (t & 1) * 8 + rr) * SM_ROW + (t >> 1) * 8);
    unsigned boffB = 2u * (((t >> 1) * 8 + rr) * SM_ROW + (t & 1) * 8);

    float acc[8][4];
    #pragma unroll
    for (int j = 0; j < 8; j++)
        #pragma unroll
        for (int r = 0; r < 4; r++) acc[j][r] = 0.0f;

    int nk = (qt + 1) * 4;

    auto load_stage = [&](int stage, int k0) {
        #pragma unroll
        for (int rep = 0; rep < 4; rep++) {
            int chunk = rep * 256 + tid;
            int plane = chunk >> 9;
            int idx = chunk & 511;
            int row = idx >> 2;
            int kc  = idx & 3;
            unsigned dst = smem_u32 +
                2u * (stage * AV_STAGE + plane * AV_A_PLANE + row * SM_ROW + kc * 8);
            const hp16* P = plane ? Alo : Ahi;
            CP16(dst, P + (size_t)(row0 + row) * T_ + k0 + kc * 8);
        }
        #pragma unroll
        for (int rep = 0; rep < 2; rep++) {
            int chunk = rep * 256 + tid;
            int plane = chunk >> 8;
            int idx = chunk & 255;
            int row = idx >> 2;
            int kc  = idx & 3;
            unsigned dst = smem_u32 +
                2u * (stage * AV_STAGE + 2 * AV_A_PLANE + plane * AV_B_PLANE + row * SM_ROW + kc * 8);
            const hp16* P = plane ? Blo : Bhi;
            CP16(dst, P + (size_t)row * T_ + k0 + kc * 8);
        }
        asm volatile("cp.async.commit_group;");
    };

    load_stage(0, 0);

    for (int kt = 0; kt < nk; kt++) {
        if (kt + 1 < nk) {
            load_stage((kt + 1) & 1, (kt + 1) << 5);
            asm volatile("cp.async.wait_group 1;");
        } else {
            asm volatile("cp.async.wait_group 0;");
        }
        __syncthreads();

        unsigned sb  = smem_u32 + (unsigned)(kt & 1) * AV_STAGE_B;
        unsigned aHi = sb + aoffB;
        unsigned aLo = aHi + 2u * AV_A_PLANE;
        unsigned bHi = sb + 4u * AV_A_PLANE + boffB;
        unsigned bLo = bHi + 2u * AV_B_PLANE;

        #pragma unroll
        for (int kk = 0; kk < 32; kk += 16) {
            uint32_t ah[4], al[4];
            ldsm4(ah, aHi + 2 * kk);
            ldsm4(al, aLo + 2 * kk);
            uint32_t bh[4][4], bl[4][4];
            #pragma unroll
            for (int p = 0; p < 4; p++) {
                ldsm4(bh[p], bHi + p * SM_TILE_B + 2 * kk);
                ldsm4(bl[p], bLo + p * SM_TILE_B + 2 * kk);
            }
            #pragma unroll
            for (int p = 0; p < 4; p++) {
                MMA16816(acc[2 * p],     ah, &bh[p][0]);
                MMA16816(acc[2 * p + 1], ah, &bh[p][2]);
            }
            #pragma unroll
            for (int p = 0; p < 4; p++) {
                MMA16816(acc[2 * p],     ah, &bl[p][0]);
                MMA16816(acc[2 * p + 1], ah, &bl[p][2]);
            }
            #pragma unroll
            for (int p = 0; p < 4; p++) {
                MMA16816(acc[2 * p],     al, &bh[p][0]);
                MMA16816(acc[2 * p + 1], al, &bh[p][2]);
            }
        }
        __syncthreads();
    }

    int r = b * T_ + row0 + warp * 16 + g;
    #pragma unroll
    for (int ni = 0; ni < 8; ni++) {
        int c = h * HD_ + ni * 8 + tg * 2;
        float vv[4] = {acc[ni][0], acc[ni][1], acc[ni][2], acc[ni][3]};
        hp16 hh[4], ll[4];
        #pragma unroll
        for (int j = 0; j < 4; j++) {
            hh[j] = f2h(vv[j]);
            ll[j] = f2h(vv[j] - h2f(hh[j]));
        }
        *(uint32_t*)(g_ohi + (size_t)r * E_ + c)       = *(uint32_t*)&hh[0];
        *(uint32_t*)(g_ohi + (size_t)(r + 8) * E_ + c) = *(uint32_t*)&hh[2];
        *(uint32_t*)(g_olo + (size_t)r * E_ + c)       = *(uint32_t*)&ll[0];
        *(uint32_t*)(g_olo + (size_t)(r + 8) * E_ + c) = *(uint32_t*)&ll[2];
    }
}

// ---------------- loss ----------------
__global__ void rowloss_kernel(const float* __restrict__ logits, const int* __restrict__ tgt) {
    int row = blockIdx.x;
    const float* lr = logits + (size_t)row * V_;
    int tid = threadIdx.x;
    float m = -1e30f;
    for (int i = tid; i < V_; i += 256) m = fmaxf(m, lr[i]);
    m = blockMax256(m);
    __syncthreads();
    float s = 0.0f;
    for (int i = tid; i < V_; i += 256) s += __expf(lr[i] - m);
    s = blockSum256(s);
    if (tid == 0)
        g_rowloss[row] = -(lr[tgt[row]] - m - logf(s));
}

__global__ void loss_final_kernel(float* __restrict__ dst) {
    int tid = threadIdx.x;
    float s = 0.0f;
    for (int i = tid; i < BT_; i += 256) s += g_rowloss[i];
    s = blockSum256(s);
    if (tid == 0) dst[0] = s * (1.0f / BT_);
}

// ---------------- host driver ----------------
#define GEMM_SMEM 92160
#define SC_SMEM   81920
#define AV_SMEM   61440

extern "C" void kernel_launch(void* const* d_in, const int* in_sizes, int n_in,
                              void* d_out, int out_size) {
    const int*   context = (const int*)  d_in[0];
    const int*   targets = (const int*)  d_in[1];
    const float* tok_emb = (const float*)d_in[2];
    const float* pos_emb = (const float*)d_in[3];
    const float* Wq    = (const float*)d_in[4];
    const float* Wk    = (const float*)d_in[5];
    const float* Wv    = (const float*)d_in[6];
    const float* Wo    = (const float*)d_in[7];
    const float* bo    = (const float*)d_in[8];
    const float* ln1_g = (const float*)d_in[9];
    const float* ln1_b = (const float*)d_in[10];
    const float* ln2_g = (const float*)d_in[11];
    const float* ln2_b = (const float*)d_in[12];
    const float* W1    = (const float*)d_in[13];
    const float* b1    = (const float*)d_in[14];
    const float* W2    = (const float*)d_in[15];
    const float* b2    = (const float*)d_in[16];
    const float* lnf_g = (const float*)d_in[17];
    const float* lnf_b = (const float*)d_in[18];
    const float* Wlm   = (const float*)d_in[19];
    const float* blm   = (const float*)d_in[20];

    float *x, *logits_sym, *lossdummy;
    hp16 *hhi, *hlo, *qkvhi, *qkvlo, *ffhi, *fflo, *ohi, *olo, *wthi, *wtlo;
    cudaGetSymbolAddress((void**)&x,   g_x);
    cudaGetSymbolAddress((void**)&logits_sym, g_logits);
    cudaGetSymbolAddress((void**)&lossdummy,  g_lossdummy);
    cudaGetSymbolAddress((void**)&hhi, g_hhi);
    cudaGetSymbolAddress((void**)&hlo, g_hlo);
    cudaGetSymbolAddress((void**)&qkvhi, g_qkvhi);
    cudaGetSymbolAddress((void**)&qkvlo, g_qkvlo);
    cudaGetSymbolAddress((void**)&ffhi, g_ffhi);
    cudaGetSymbolAddress((void**)&fflo, g_fflo);
    cudaGetSymbolAddress((void**)&ohi, g_ohi);
    cudaGetSymbolAddress((void**)&olo, g_olo);
    cudaGetSymbolAddress((void**)&wthi, g_wthi);
    cudaGetSymbolAddress((void**)&wtlo, g_wtlo);

    cudaFuncSetAttribute(mma_gemm, cudaFuncAttributeMaxDynamicSharedMemorySize, GEMM_SMEM);
    cudaFuncSetAttribute(attn_scores_mma, cudaFuncAttributeMaxDynamicSharedMemorySize, SC_SMEM);
    cudaFuncSetAttribute(attn_av_mma, cudaFuncAttributeMaxDynamicSharedMemorySize, AV_SMEM);

    const long long BTV = (long long)BT_ * V_;
    float* out = (float*)d_out;
    float* logits = ((long long)out_size >= BTV) ? out : logits_sym;
    float* lossdst;
    if ((long long)out_size > BTV)       lossdst = out + BTV;
    else if ((long long)out_size < BTV)  lossdst = out;
    else                                 lossdst = lossdummy;

    embed_kernel<<<(BT_ * E_) / 256, 256>>>(context, tok_emb, pos_emb);

    dim3 gQKV(3 * E_ / 128, BT_ / 128);
    dim3 gE(E_ / 128, BT_ / 128);
    dim3 gFF(FF_ / 128, BT_ / 128);
    dim3 gV2(V_ / 128, BT_ / 128);
    dim3 gSc(T_ / 128, T_ / 128, B_ * H_);
    dim3 gAV(1, T_ / 128, B_ * H_);
    dim3 gVT(T_ / 32, HD_ / 32, B_ * H_);
    dim3 tT(8, 32);
    dim3 tVT(32, 32);

    for (int l = 0; l < L_; l++) {
        const float* wq = Wq + (size_t)l * E_ * E_;
        const float* wk = Wk + (size_t)l * E_ * E_;
        const float* wv = Wv + (size_t)l * E_ * E_;
        const float* wo = Wo + (size_t)l * E_ * E_;
        const float* w1 = W1 + (size_t)l * E_ * FF_;
        const float* w2 = W2 + (size_t)l * FF_ * E_;

        // ---- attention block ----
        ln_split_kernel<<<BT_, 256>>>(x, hhi, hlo, ln1_g + l * E_, ln1_b + l * E_);
        wt_tsplit<<<dim3(E_ / 32, E_ / 32), tT>>>(wq, wthi,                       wtlo,                       E_, E_);
        wt_tsplit<<<dim3(E_ / 32, E_ / 32), tT>>>(wk, wthi + (size_t)E_ * E_,     wtlo + (size_t)E_ * E_,     E_, E_);
        wt_tsplit<<<dim3(E_ / 32, E_ / 32), tT>>>(wv, wthi + (size_t)2 * E_ * E_, wtlo + (size_t)2 * E_ * E_, E_, E_);
        mma_gemm<<<gQKV, 256, GEMM_SMEM>>>(hhi, hlo, E_, wthi, wtlo, E_,
                                           nullptr, nullptr, nullptr, qkvhi, qkvlo,
                                           3 * E_, E_, 0);
        vt_tsplit_kernel<<<gVT, tVT>>>();
        attn_scores_mma<<<gSc, 256, SC_SMEM>>>();
        softmax_split_kernel<<<B_ * H_ * T_, 256>>>();
        attn_av_mma<<<gAV, 256, AV_SMEM>>>();
        wt_tsplit<<<dim3(E_ / 32, E_ / 32), tT>>>(wo, wthi, wtlo, E_, E_);
        mma_gemm<<<gE, 256, GEMM_SMEM>>>(ohi, olo, E_, wthi, wtlo, E_,
                                         bo + l * E_, x, x, nullptr, nullptr,
                                         E_, E_, 0);

        // ---- MLP block ----
        ln_split_kernel<<<BT_, 256>>>(x, hhi, hlo, ln2_g + l * E_, ln2_b + l * E_);
        wt_tsplit<<<dim3(FF_ / 32, E_ / 32), tT>>>(w1, wthi, wtlo, FF_, E_);
        mma_gemm<<<gFF, 256, GEMM_SMEM>>>(hhi, hlo, E_, wthi, wtlo, E_,
                                          b1 + l * FF_, nullptr, nullptr, ffhi, fflo,
                                          FF_, E_, 1);
        wt_tsplit<<<dim3(E_ / 32, FF_ / 32), tT>>>(w2, wthi, wtlo, E_, FF_);
        mma_gemm<<<gE, 256, GEMM_SMEM>>>(ffhi, fflo, FF_, wthi, wtlo, FF_,
                                         b2 + l * E_, x, x, nullptr, nullptr,
                                         E_, FF_, 0);
    }

    // ---- final LN + LM head ----
    ln_split_kernel<<<BT_, 256>>>(x, hhi, hlo, lnf_g, lnf_b);
    wt_tsplit<<<dim3(V_ / 32, E_ / 32), tT>>>(Wlm, wthi, wtlo, V_, E_);
    mma_gemm<<<gV2, 256, GEMM_SMEM>>>(hhi, hlo, E_, wthi, wtlo, E_,
                                      blm, nullptr, logits, nullptr, nullptr,
                                      V_, E_, 0);

    rowloss_kernel<<<BT_, 256>>>(logits, targets);
    loss_final_kernel<<<1, 256>>>(lossdst);
}

// round 15
// speedup vs baseline: 1.2901x; 1.2901x over previous
#include <cuda_runtime.h>
#include <cuda_bf16.h>
#include <stdint.h>
#include <math.h>

// ---------------- problem constants ----------------
#define B_   2
#define T_   1024
#define E_   1024
#define H_   16
#define HD_  64
#define L_   8
#define FF_  4096
#define V_   32000
#define BT_  (B_ * T_)
#define EPS_ 1e-5f
#define SCALE_ 0.03125f   // 1/sqrt(E)

typedef __nv_bfloat16 bf16;

// ---------------- scratch (device globals) ----------------
__device__ float g_x[BT_ * E_];
__device__ float g_logits[(size_t)BT_ * V_];
__device__ float g_rowloss[BT_];
__device__ float g_lossdummy[4];
__device__ bf16 g_hhi[BT_ * E_];
__device__ bf16 g_hlo[BT_ * E_];
__device__ bf16 g_qkvhi[BT_ * 3 * E_];
__device__ bf16 g_qkvlo[BT_ * 3 * E_];
__device__ bf16 g_vthi[(size_t)B_ * H_ * HD_ * T_];
__device__ bf16 g_vtlo[(size_t)B_ * H_ * HD_ * T_];
__device__ bf16 g_ffhi[(size_t)BT_ * FF_];
__device__ bf16 g_fflo[(size_t)BT_ * FF_];
__device__ bf16 g_ohi[BT_ * E_];
__device__ bf16 g_olo[BT_ * E_];
__device__ bf16 g_wthi[(size_t)V_ * E_];
__device__ bf16 g_wtlo[(size_t)V_ * E_];

// single dynamic-shared symbol for all kernels
extern __shared__ bf16 smem[];

// ---------------- reductions (blockDim.x == 256) ----------------
__device__ __forceinline__ float blockSum256(float v) {
    __shared__ float sh[8];
    int tid = threadIdx.x;
    #pragma unroll
    for (int o = 16; o; o >>= 1) v += __shfl_xor_sync(0xffffffffu, v, o);
    __syncthreads();
    if ((tid & 31) == 0) sh[tid >> 5] = v;
    __syncthreads();
    v = sh[tid & 7];
    #pragma unroll
    for (int o = 4; o; o >>= 1) v += __shfl_xor_sync(0xffffffffu, v, o);
    return v;
}

__device__ __forceinline__ float blockMax256(float v) {
    __shared__ float sh[8];
    int tid = threadIdx.x;
    #pragma unroll
    for (int o = 16; o; o >>= 1) v = fmaxf(v, __shfl_xor_sync(0xffffffffu, v, o));
    __syncthreads();
    if ((tid & 31) == 0) sh[tid >> 5] = v;
    __syncthreads();
    v = sh[tid & 7];
    #pragma unroll
    for (int o = 4; o; o >>= 1) v = fmaxf(v, __shfl_xor_sync(0xffffffffu, v, o));
    return v;
}

// ---------------- embedding ----------------
__global__ void embed_kernel(const int* __restrict__ ctx,
                             const float* __restrict__ tok,
                             const float* __restrict__ pos) {
    int gid = blockIdx.x * blockDim.x + threadIdx.x;
    int bt = gid >> 10;
    int e  = gid & (E_ - 1);
    int t  = bt & (T_ - 1);
    g_x[gid] = tok[(size_t)ctx[bt] * E_ + e] + pos[t * E_ + e];
}

// ---------------- layernorm -> split bf16 hi/lo planes ----------------
__global__ void ln_split_kernel(const float* __restrict__ in,
                                bf16* __restrict__ hhi, bf16* __restrict__ hlo,
                                const float* __restrict__ g, const float* __restrict__ b) {
    int row = blockIdx.x;
    int tid = threadIdx.x;
    const float4* rp = (const float4*)(in + (size_t)row * E_);
    float4 v = rp[tid];
    float s  = v.x + v.y + v.z + v.w;
    float ss = v.x * v.x + v.y * v.y + v.z * v.z + v.w * v.w;
    s  = blockSum256(s);
    __syncthreads();
    ss = blockSum256(ss);
    float mean = s * (1.0f / E_);
    float var  = ss * (1.0f / E_) - mean * mean;
    float inv  = rsqrtf(var + EPS_);
    int e = tid * 4;
    float o[4];
    o[0] = (v.x - mean) * inv * g[e + 0] + b[e + 0];
    o[1] = (v.y - mean) * inv * g[e + 1] + b[e + 1];
    o[2] = (v.z - mean) * inv * g[e + 2] + b[e + 2];
    o[3] = (v.w - mean) * inv * g[e + 3] + b[e + 3];
    ushort4 ho, lw;
    unsigned short* hp = &ho.x;
    unsigned short* lp = &lw.x;
    #pragma unroll
    for (int j = 0; j < 4; j++) {
        bf16 h = __float2bfloat16(o[j]);
        bf16 l = __float2bfloat16(o[j] - __bfloat162float(h));
        hp[j] = __bfloat16_as_ushort(h);
        lp[j] = __bfloat16_as_ushort(l);
    }
    ((ushort4*)(hhi + (size_t)row * E_))[tid] = ho;
    ((ushort4*)(hlo + (size_t)row * E_))[tid] = lw;
}

// ---------------- weight transpose+split ----------------
__global__ void wt_tsplit(const float* __restrict__ W,
                          bf16* __restrict__ Thi, bf16* __restrict__ Tlo,
                          int N, int K) {
    __shared__ float s[32][33];
    int n0 = blockIdx.x * 32;
    int k0 = blockIdx.y * 32;
    int tx = threadIdx.x;   // 0..7
    int ty = threadIdx.y;   // 0..31
    float4 rv = *(const float4*)(W + (size_t)(k0 + ty) * N + n0 + tx * 4);
    s[ty][tx * 4 + 0] = rv.x;
    s[ty][tx * 4 + 1] = rv.y;
    s[ty][tx * 4 + 2] = rv.z;
    s[ty][tx * 4 + 3] = rv.w;
    __syncthreads();
    ushort4 ho, lw;
    unsigned short* hp = &ho.x;
    unsigned short* lp = &lw.x;
    #pragma unroll
    for (int j = 0; j < 4; j++) {
        float f = s[tx * 4 + j][ty];
        bf16 h = __float2bfloat16(f);
        bf16 l = __float2bfloat16(f - __bfloat162float(h));
        hp[j] = __bfloat16_as_ushort(h);
        lp[j] = __bfloat16_as_ushort(l);
    }
    size_t off = (size_t)(n0 + ty) * K + k0 + tx * 4;
    *(ushort4*)(Thi + off) = ho;
    *(ushort4*)(Tlo + off) = lw;
}

// ---------------- V transpose per head ----------------
__global__ void vt_tsplit_kernel() {
    __shared__ bf16 sh[32][33];
    __shared__ bf16 sl[32][33];
    int z = blockIdx.z;  int b = z >> 4;  int h = z & 15;
    int t0 = blockIdx.x * 32, d0 = blockIdx.y * 32;
    int tx = threadIdx.x, ty = threadIdx.y;
    size_t src = (size_t)(b * T_ + t0 + ty) * (3 * E_) + 2 * E_ + h * HD_ + d0 + tx;
    sh[ty][tx] = g_qkvhi[src];
    sl[ty][tx] = g_qkvlo[src];
    __syncthreads();
    size_t dst = (size_t)(z * HD_ + d0 + ty) * T_ + t0 + tx;
    g_vthi[dst] = sh[tx][ty];
    g_vtlo[dst] = sl[tx][ty];
}

// ============ MMA helpers ============
#define MMA16816(c, a, b) \
  asm volatile("mma.sync.aligned.m16n8k16.row.col.f32.bf16.bf16.f32 " \
    "{%0,%1,%2,%3}, {%4,%5,%6,%7}, {%8,%9}, {%0,%1,%2,%3};" \
    : "+f"((c)[0]), "+f"((c)[1]), "+f"((c)[2]), "+f"((c)[3]) \
    : "r"((a)[0]), "r"((a)[1]), "r"((a)[2]), "r"((a)[3]), \
      "r"((b)[0]), "r"((b)[1]))

#define CP16(dst_u32, src) \
  asm volatile("cp.async.cg.shared.global [%0], [%1], 16;" :: "r"(dst_u32), "l"(src))

__device__ __forceinline__ void ldsm4(uint32_t* r, unsigned a) {
    asm volatile("ldmatrix.sync.aligned.m8n8.x4.shared.b16 {%0,%1,%2,%3}, [%4];"
        : "=r"(r[0]), "=r"(r[1]), "=r"(r[2]), "=r"(r[3]) : "r"(a));
}

__device__ __forceinline__ void splitpack2(const float* v, uint32_t& hi, uint32_t& lo) {
    bf16 h0 = __float2bfloat16(v[0]);
    bf16 h1 = __float2bfloat16(v[1]);
    hi = (uint32_t)__bfloat16_as_ushort(h0) | ((uint32_t)__bfloat16_as_ushort(h1) << 16);
    bf16 l0 = __float2bfloat16(v[0] - __bfloat162float(h0));
    bf16 l1 = __float2bfloat16(v[1] - __bfloat162float(h1));
    lo = (uint32_t)__bfloat16_as_ushort(l0) | ((uint32_t)__bfloat16_as_ushort(l1) << 16);
}

#define SM_STAGE 20480
#define SM_MAT   5120
#define SM_ROW   40
#define SM_STAGE_B 40960u
#define SM_MAT_B   10240u
#define SM_TILE_B  1280u

// ============ bf16x3 GEMM, 128x128x32, 3-stage cp.async, ldmatrix, term-major ======
__global__ void __launch_bounds__(256, 1) mma_gemm(
        const bf16* __restrict__ Ahi, const bf16* __restrict__ Alo, int lda,
        const bf16* __restrict__ Bthi, const bf16* __restrict__ Btlo, int ldb,
        const float* __restrict__ bias, const float* __restrict__ res,
        float* __restrict__ C, bf16* __restrict__ Chi, bf16* __restrict__ Clo,
        int ldc, int K, int doRelu) {
    int tid  = threadIdx.x;
    int warp = tid >> 5, lane = tid & 31;
    int wm = warp & 3;
    int wn = warp >> 2;
    int g  = lane >> 2;
    int tg = lane & 3;
    int t  = lane >> 3, rr = lane & 7;

    int row0 = blockIdx.y * 128;
    int col0 = blockIdx.x * 128;

    const bf16* planes[4] = {Ahi, Alo, Bthi, Btlo};
    int lds[4] = {lda, lda, ldb, ldb};
    unsigned smem_u32 = (unsigned)__cvta_generic_to_shared(smem);

    unsigned aoffB = 2u * ((wm * 32 + (t & 1) * 8 + rr) * SM_ROW + (t >> 1) * 8);
    unsigned boffB = 2u * ((wn * 64 + (t >> 1) * 8 + rr) * SM_ROW + (t & 1) * 8);

    float acc[2][8][4];
    #pragma unroll
    for (int i = 0; i < 2; i++)
        #pragma unroll
        for (int j = 0; j < 8; j++)
            #pragma unroll
            for (int r = 0; r < 4; r++) acc[i][j][r] = 0.0f;

    int nk = K >> 5;

    auto load_stage = [&](int stage, int k0) {
        #pragma unroll
        for (int m = 0; m < 4; m++) {
            const bf16* P = planes[m];
            int base_row = (m < 2) ? row0 : col0;
            int ld = lds[m];
            #pragma unroll
            for (int rep = 0; rep < 2; rep++) {
                int chunk = rep * 256 + tid;
                int row = chunk >> 2;
                int kc  = chunk & 3;
                unsigned dst = smem_u32 +
                    2u * (stage * SM_STAGE + m * SM_MAT + row * SM_ROW + kc * 8);
                const bf16* src = P + (size_t)(base_row + row) * ld + k0 + kc * 8;
                CP16(dst, src);
            }
        }
        asm volatile("cp.async.commit_group;");
    };

    load_stage(0, 0);
    if (nk > 1) load_stage(1, 32);

    for (int kt = 0; kt < nk; kt++) {
        if (kt + 1 < nk) { asm volatile("cp.async.wait_group 1;"); }
        else             { asm volatile("cp.async.wait_group 0;"); }
        __syncthreads();

        unsigned sb  = smem_u32 + (unsigned)(kt % 3) * SM_STAGE_B;
        unsigned aHi = sb + aoffB;
        unsigned aLo = aHi + SM_MAT_B;
        unsigned bHi = sb + 2u * SM_MAT_B + boffB;
        unsigned bLo = bHi + SM_MAT_B;

        #pragma unroll
        for (int kk = 0; kk < 32; kk += 16) {
            uint32_t ah[2][4], al[2][4];
            ldsm4(ah[0], aHi + 2 * kk);
            ldsm4(ah[1], aHi + SM_TILE_B + 2 * kk);
            ldsm4(al[0], aLo + 2 * kk);
            ldsm4(al[1], aLo + SM_TILE_B + 2 * kk);
            uint32_t bh[4][4], bl[4][4];
            #pragma unroll
            for (int p = 0; p < 4; p++) {
                ldsm4(bh[p], bHi + p * SM_TILE_B + 2 * kk);
                ldsm4(bl[p], bLo + p * SM_TILE_B + 2 * kk);
            }
            #pragma unroll
            for (int p = 0; p < 4; p++)
                #pragma unroll
                for (int mi = 0; mi < 2; mi++) {
                    MMA16816(acc[mi][2 * p],     ah[mi], &bh[p][0]);
                    MMA16816(acc[mi][2 * p + 1], ah[mi], &bh[p][2]);
                }
            #pragma unroll
            for (int p = 0; p < 4; p++)
                #pragma unroll
                for (int mi = 0; mi < 2; mi++) {
                    MMA16816(acc[mi][2 * p],     ah[mi], &bl[p][0]);
                    MMA16816(acc[mi][2 * p + 1], ah[mi], &bl[p][2]);
                }
            #pragma unroll
            for (int p = 0; p < 4; p++)
                #pragma unroll
                for (int mi = 0; mi < 2; mi++) {
                    MMA16816(acc[mi][2 * p],     al[mi], &bh[p][0]);
                    MMA16816(acc[mi][2 * p + 1], al[mi], &bh[p][2]);
                }
        }
        __syncthreads();
        if (kt + 2 < nk) load_stage((kt + 2) % 3, (kt + 2) << 5);
    }

    // ---- epilogue ----
    #pragma unroll
    for (int mi = 0; mi < 2; mi++) {
        int r = row0 + wm * 32 + mi * 16 + g;
        #pragma unroll
        for (int ni = 0; ni < 8; ni++) {
            int c = col0 + wn * 64 + ni * 8 + tg * 2;
            float v0 = acc[mi][ni][0], v1 = acc[mi][ni][1];
            float v2 = acc[mi][ni][2], v3 = acc[mi][ni][3];
            if (bias) {
                float b0 = bias[c], b1 = bias[c + 1];
                v0 += b0; v1 += b1; v2 += b0; v3 += b1;
            }
            if (doRelu) {
                v0 = fmaxf(v0, 0.0f); v1 = fmaxf(v1, 0.0f);
                v2 = fmaxf(v2, 0.0f); v3 = fmaxf(v3, 0.0f);
            }
            if (Chi) {
                float vv0[2] = {v0, v1}, vv1[2] = {v2, v3};
                uint32_t h0, l0, h1, l1;
                splitpack2(vv0, h0, l0);
                splitpack2(vv1, h1, l1);
                *(uint32_t*)(Chi + (size_t)r * ldc + c)       = h0;
                *(uint32_t*)(Chi + (size_t)(r + 8) * ldc + c) = h1;
                *(uint32_t*)(Clo + (size_t)r * ldc + c)       = l0;
                *(uint32_t*)(Clo + (size_t)(r + 8) * ldc + c) = l1;
            } else {
                if (res) {
                    v0 += res[(size_t)r * ldc + c];
                    v1 += res[(size_t)r * ldc + c + 1];
                    v2 += res[(size_t)(r + 8) * ldc + c];
                    v3 += res[(size_t)(r + 8) * ldc + c + 1];
                }
                *(float2*)(C + (size_t)r * ldc + c)       = make_float2(v0, v1);
                *(float2*)(C + (size_t)(r + 8) * ldc + c) = make_float2(v2, v3);
            }
        }
    }
}

// ============ fused flash attention (causal, bf16x3, online softmax) ============
// CTA per (z, qt): Q block 128 rows. K/V tiles streamed, double-buffered.
// smem layout (halves):
#define FQ_ROW   72
#define FQ_PLANE (128 * FQ_ROW)              // 9216
#define FV_ROW   136
#define FV_PLANE (64 * FV_ROW)               // 8704
#define FK_BASE  (2 * FQ_PLANE)              // 18432
#define FV_BASE  (FK_BASE + 4 * FQ_PLANE)    // 55296
#define FRED_OFF (FV_BASE + 4 * FV_PLANE)    // 90112 halves
#define FL_SMEM  (FRED_OFF * 2 + 4 * 128 * 4)  // 180224 + 2048 = 182272 bytes

__global__ void __launch_bounds__(256, 1) flash_attn() {
    int z = blockIdx.x;
    int qt = 7 - blockIdx.y;      // big tiles first
    int b = z >> 4, h = z & 15;
    int tid = threadIdx.x, warp = tid >> 5, lane = tid & 31;
    int wm = warp & 3, wn = warp >> 2;
    int g = lane >> 2, tg = lane & 3;
    int t = lane >> 3, rr = lane & 7;
    int row0 = qt * 128;

    unsigned sb = (unsigned)__cvta_generic_to_shared(smem);
    float* rmax = (float*)(smem + FRED_OFF);        // [2][128]
    float* rsum = rmax + 256;                       // [2][128]

    const bf16* Qh = g_qkvhi + (size_t)b * T_ * 3 * E_ + h * HD_;
    const bf16* Ql = g_qkvlo + (size_t)b * T_ * 3 * E_ + h * HD_;
    const bf16* Kh = Qh + E_;
    const bf16* Kl = Ql + E_;
    const bf16* Vh = g_vthi + (size_t)z * HD_ * T_;
    const bf16* Vl = g_vtlo + (size_t)z * HD_ * T_;

    // ---- load Q (once) + KV stage 0, one commit group ----
    #pragma unroll
    for (int i = 0; i < 8; i++) {
        int idx = i * 256 + tid;         // 2048 chunks: plane x 128row x 8c
        int plane = idx >> 10;
        int rem = idx & 1023;
        int r = rem >> 3, c = rem & 7;
        unsigned dst = sb + 2u * ((unsigned)plane * FQ_PLANE + r * FQ_ROW + c * 8);
        const bf16* P = plane ? Ql : Qh;
        CP16(dst, P + (size_t)(row0 + r) * (3 * E_) + c * 8);
    }
    auto load_kv = [&](int stage, int kt) {
        #pragma unroll
        for (int i = 0; i < 8; i++) {    // K: 2048 chunks
            int idx = i * 256 + tid;
            int plane = idx >> 10;
            int rem = idx & 1023;
            int r = rem >> 3, c = rem & 7;
            unsigned dst = sb + 2u * ((unsigned)(FK_BASE + stage * 2 * FQ_PLANE)
                                      + (unsigned)plane * FQ_PLANE + r * FQ_ROW + c * 8);
            const bf16* P = plane ? Kl : Kh;
            CP16(dst, P + (size_t)(kt * 128 + r) * (3 * E_) + c * 8);
        }
        #pragma unroll
        for (int i = 0; i < 8; i++) {    // V: 2048 chunks (64 rows x 16 chunks)
            int idx = i * 256 + tid;
            int plane = idx >> 10;
            int rem = idx & 1023;
            int r = rem >> 4, c = rem & 15;
            unsigned dst = sb + 2u * ((unsigned)(FV_BASE + stage * 2 * FV_PLANE)
                                      + (unsigned)plane * FV_PLANE + r * FV_ROW + c * 8);
            const bf16* P = plane ? Vl : Vh;
            CP16(dst, P + (size_t)r * T_ + kt * 128 + c * 8);
        }
        asm volatile("cp.async.commit_group;");
    };
    load_kv(0, 0);
    asm volatile("cp.async.commit_group;");   // group boundary after {Q, KV0}? (Q+KV0 committed in load_kv's commit; this is an empty group, harmless)

    unsigned aoffB = 2u * ((wm * 32 + (t & 1) * 8 + rr) * FQ_ROW + (t >> 1) * 8);
    unsigned boffB = 2u * ((wn * 64 + (t >> 1) * 8 + rr) * FQ_ROW + (t & 1) * 8);
    unsigned voffB = 2u * (((t >> 1) * 8 + rr) * FV_ROW + (t & 1) * 8);

    float acc_o[2][8][4];
    #pragma unroll
    for (int i = 0; i < 2; i++)
        #pragma unroll
        for (int j = 0; j < 8; j++)
            #pragma unroll
            for (int r = 0; r < 4; r++) acc_o[i][j][r] = 0.0f;
    float m_run[2][2] = {{-1e30f, -1e30f}, {-1e30f, -1e30f}};
    float l_run[2][2] = {{0.0f, 0.0f}, {0.0f, 0.0f}};

    int myrow[2][2];
    #pragma unroll
    for (int mi = 0; mi < 2; mi++)
        #pragma unroll
        for (int hh = 0; hh < 2; hh++)
            myrow[mi][hh] = wm * 32 + mi * 16 + g + hh * 8;

    for (int kt = 0; kt <= qt; kt++) {
        if (kt + 1 <= qt) load_kv((kt + 1) & 1, kt + 1);
        if (kt + 1 <= qt) { asm volatile("cp.async.wait_group 1;"); }
        else              { asm volatile("cp.async.wait_group 0;"); }
        __syncthreads();

        // ---- S = Q K^T (3-term) ----
        float acc_s[2][8][4];
        #pragma unroll
        for (int i = 0; i < 2; i++)
            #pragma unroll
            for (int j = 0; j < 8; j++)
                #pragma unroll
                for (int r = 0; r < 4; r++) acc_s[i][j][r] = 0.0f;

        unsigned qHi = sb + aoffB;
        unsigned qLo = qHi + 2u * FQ_PLANE;
        unsigned kHi = sb + 2u * (FK_BASE + (unsigned)(kt & 1) * 2 * FQ_PLANE) + boffB;
        unsigned kLo = kHi + 2u * FQ_PLANE;

        #pragma unroll
        for (int kk = 0; kk < 64; kk += 16) {
            uint32_t ah[2][4], al[2][4];
            ldsm4(ah[0], qHi + 2 * kk);
            ldsm4(ah[1], qHi + 16 * FQ_ROW * 2 + 2 * kk);
            ldsm4(al[0], qLo + 2 * kk);
            ldsm4(al[1], qLo + 16 * FQ_ROW * 2 + 2 * kk);
            uint32_t bh[4][4], bl[4][4];
            #pragma unroll
            for (int p = 0; p < 4; p++) {
                ldsm4(bh[p], kHi + p * (16 * FQ_ROW * 2) + 2 * kk);
                ldsm4(bl[p], kLo + p * (16 * FQ_ROW * 2) + 2 * kk);
            }
            #pragma unroll
            for (int p = 0; p < 4; p++)
                #pragma unroll
                for (int mi = 0; mi < 2; mi++) {
                    MMA16816(acc_s[mi][2 * p],     ah[mi], &bh[p][0]);
                    MMA16816(acc_s[mi][2 * p + 1], ah[mi], &bh[p][2]);
                }
            #pragma unroll
            for (int p = 0; p < 4; p++)
                #pragma unroll
                for (int mi = 0; mi < 2; mi++) {
                    MMA16816(acc_s[mi][2 * p],     ah[mi], &bl[p][0]);
                    MMA16816(acc_s[mi][2 * p + 1], ah[mi], &bl[p][2]);
                }
            #pragma unroll
            for (int p = 0; p < 4; p++)
                #pragma unroll
                for (int mi = 0; mi < 2; mi++) {
                    MMA16816(acc_s[mi][2 * p],     al[mi], &bh[p][0]);
                    MMA16816(acc_s[mi][2 * p + 1], al[mi], &bh[p][2]);
                }
        }

        // ---- scale + causal mask ----
        if (kt == qt) {
            #pragma unroll
            for (int mi = 0; mi < 2; mi++)
                #pragma unroll
                for (int ni = 0; ni < 8; ni++)
                    #pragma unroll
                    for (int j = 0; j < 4; j++) {
                        int col = wn * 64 + ni * 8 + tg * 2 + (j & 1);   // local (same tile)
                        int rw  = myrow[mi][j >> 1];
                        acc_s[mi][ni][j] = (col > rw) ? -1e30f
                                          : acc_s[mi][ni][j] * SCALE_;
                    }
        } else {
            #pragma unroll
            for (int mi = 0; mi < 2; mi++)
                #pragma unroll
                for (int ni = 0; ni < 8; ni++)
                    #pragma unroll
                    for (int j = 0; j < 4; j++)
                        acc_s[mi][ni][j] *= SCALE_;
        }

        // ---- row max ----
        float lm[2][2] = {{-1e30f, -1e30f}, {-1e30f, -1e30f}};
        #pragma unroll
        for (int mi = 0; mi < 2; mi++)
            #pragma unroll
            for (int ni = 0; ni < 8; ni++)
                #pragma unroll
                for (int j = 0; j < 4; j++)
                    lm[mi][j >> 1] = fmaxf(lm[mi][j >> 1], acc_s[mi][ni][j]);
        #pragma unroll
        for (int mi = 0; mi < 2; mi++)
            #pragma unroll
            for (int hh = 0; hh < 2; hh++) {
                float v = lm[mi][hh];
                v = fmaxf(v, __shfl_xor_sync(0xffffffffu, v, 1));
                v = fmaxf(v, __shfl_xor_sync(0xffffffffu, v, 2));
                lm[mi][hh] = v;
                if (tg == 0) rmax[wn * 128 + myrow[mi][hh]] = v;
            }
        __syncthreads();
        float m_new[2][2], factor[2][2];
        #pragma unroll
        for (int mi = 0; mi < 2; mi++)
            #pragma unroll
            for (int hh = 0; hh < 2; hh++) {
                float tm = fmaxf(rmax[myrow[mi][hh]], rmax[128 + myrow[mi][hh]]);
                m_new[mi][hh] = fmaxf(m_run[mi][hh], tm);
                factor[mi][hh] = __expf(m_run[mi][hh] - m_new[mi][hh]);
            }

        // ---- exp + row sum ----
        float ls[2][2] = {{0.0f, 0.0f}, {0.0f, 0.0f}};
        #pragma unroll
        for (int mi = 0; mi < 2; mi++)
            #pragma unroll
            for (int ni = 0; ni < 8; ni++)
                #pragma unroll
                for (int j = 0; j < 4; j++) {
                    float e = __expf(acc_s[mi][ni][j] - m_new[mi][j >> 1]);
                    acc_s[mi][ni][j] = e;
                    ls[mi][j >> 1] += e;
                }
        #pragma unroll
        for (int mi = 0; mi < 2; mi++)
            #pragma unroll
            for (int hh = 0; hh < 2; hh++) {
                float v = ls[mi][hh];
                v += __shfl_xor_sync(0xffffffffu, v, 1);
                v += __shfl_xor_sync(0xffffffffu, v, 2);
                ls[mi][hh] = v;
                if (tg == 0) rsum[wn * 128 + myrow[mi][hh]] = v;
            }
        __syncthreads();
        #pragma unroll
        for (int mi = 0; mi < 2; mi++)
            #pragma unroll
            for (int hh = 0; hh < 2; hh++) {
                float srow = rsum[myrow[mi][hh]] + rsum[128 + myrow[mi][hh]];
                l_run[mi][hh] = l_run[mi][hh] * factor[mi][hh] + srow;
                m_run[mi][hh] = m_new[mi][hh];
            }

        // ---- rescale O ----
        #pragma unroll
        for (int mi = 0; mi < 2; mi++)
            #pragma unroll
            for (int no = 0; no < 8; no++)
                #pragma unroll
                for (int j = 0; j < 4; j++)
                    acc_o[mi][no][j] *= factor[mi][j >> 1];

        // ---- O += P V (3-term) ----
        unsigned vHiB = sb + 2u * (FV_BASE + (unsigned)(kt & 1) * 2 * FV_PLANE) + voffB;
        unsigned vLoB = vHiB + 2u * FV_PLANE;
        #pragma unroll
        for (int p = 0; p < 4; p++) {
            uint32_t ph[2][4], pl[2][4];
            #pragma unroll
            for (int mi = 0; mi < 2; mi++) {
                splitpack2(&acc_s[mi][2 * p][0],     ph[mi][0], pl[mi][0]);
                splitpack2(&acc_s[mi][2 * p][2],     ph[mi][1], pl[mi][1]);
                splitpack2(&acc_s[mi][2 * p + 1][0], ph[mi][2], pl[mi][2]);
                splitpack2(&acc_s[mi][2 * p + 1][2], ph[mi][3], pl[mi][3]);
            }
            unsigned kcol = 2u * (wn * 64 + p * 16);
            #pragma unroll
            for (int po = 0; po < 4; po++) {
                uint32_t bh[4], bl[4];
                ldsm4(bh, vHiB + po * (16 * FV_ROW * 2) + kcol);
                ldsm4(bl, vLoB + po * (16 * FV_ROW * 2) + kcol);
                #pragma unroll
                for (int mi = 0; mi < 2; mi++) {
                    MMA16816(acc_o[mi][2 * po],     ph[mi], &bh[0]);
                    MMA16816(acc_o[mi][2 * po + 1], ph[mi], &bh[2]);
                    MMA16816(acc_o[mi][2 * po],     ph[mi], &bl[0]);
                    MMA16816(acc_o[mi][2 * po + 1], ph[mi], &bl[2]);
                    MMA16816(acc_o[mi][2 * po],     pl[mi], &bh[0]);
                    MMA16816(acc_o[mi][2 * po + 1], pl[mi], &bh[2]);
                }
            }
        }
        __syncthreads();   // protect K/V smem reuse by next prefetch
    }

    // ---- combine wn partials, normalize, write split o planes ----
    float* osh = (float*)smem;    // 128 x 64 fp32 = 32KB
    __syncthreads();
    if (wn == 1) {
        #pragma unroll
        for (int mi = 0; mi < 2; mi++)
            #pragma unroll
            for (int no = 0; no < 8; no++)
                #pragma unroll
                for (int j = 0; j < 4; j++) {
                    int rw = myrow[mi][j >> 1];
                    int cl = no * 8 + tg * 2 + (j & 1);
                    osh[rw * 64 + cl] = acc_o[mi][no][j];
                }
    }
    __syncthreads();
    if (wn == 0) {
        #pragma unroll
        for (int mi = 0; mi < 2; mi++)
            #pragma unroll
            for (int hh = 0; hh < 2; hh++) {
                float invl = 1.0f / l_run[mi][hh];
                int rw = myrow[mi][hh];
                int rglob = b * T_ + row0 + rw;
                #pragma unroll
                for (int no = 0; no < 8; no++) {
                    int cl = no * 8 + tg * 2;
                    float vv[2];
                    vv[0] = (acc_o[mi][no][hh * 2 + 0] + osh[rw * 64 + cl])     * invl;
                    vv[1] = (acc_o[mi][no][hh * 2 + 1] + osh[rw * 64 + cl + 1]) * invl;
                    uint32_t hi, lo;
                    splitpack2(vv, hi, lo);
                    *(uint32_t*)(g_ohi + (size_t)rglob * E_ + h * HD_ + cl) = hi;
                    *(uint32_t*)(g_olo + (size_t)rglob * E_ + h * HD_ + cl) = lo;
                }
            }
    }
}

// ---------------- loss ----------------
__global__ void rowloss_kernel(const float* __restrict__ logits, const int* __restrict__ tgt) {
    int row = blockIdx.x;
    const float* lr = logits + (size_t)row * V_;
    int tid = threadIdx.x;
    float m = -1e30f;
    for (int i = tid; i < V_; i += 256) m = fmaxf(m, lr[i]);
    m = blockMax256(m);
    __syncthreads();
    float s = 0.0f;
    for (int i = tid; i < V_; i += 256) s += __expf(lr[i] - m);
    s = blockSum256(s);
    if (tid == 0)
        g_rowloss[row] = -(lr[tgt[row]] - m - logf(s));
}

__global__ void loss_final_kernel(float* __restrict__ dst) {
    int tid = threadIdx.x;
    float s = 0.0f;
    for (int i = tid; i < BT_; i += 256) s += g_rowloss[i];
    s = blockSum256(s);
    if (tid == 0) dst[0] = s * (1.0f / BT_);
}

// ---------------- host driver ----------------
#define GEMM_SMEM 122880

extern "C" void kernel_launch(void* const* d_in, const int* in_sizes, int n_in,
                              void* d_out, int out_size) {
    const int*   context = (const int*)  d_in[0];
    const int*   targets = (const int*)  d_in[1];
    const float* tok_emb = (const float*)d_in[2];
    const float* pos_emb = (const float*)d_in[3];
    const float* Wq    = (const float*)d_in[4];
    const float* Wk    = (const float*)d_in[5];
    const float* Wv    = (const float*)d_in[6];
    const float* Wo    = (const float*)d_in[7];
    const float* bo    = (const float*)d_in[8];
    const float* ln1_g = (const float*)d_in[9];
    const float* ln1_b = (const float*)d_in[10];
    const float* ln2_g = (const float*)d_in[11];
    const float* ln2_b = (const float*)d_in[12];
    const float* W1    = (const float*)d_in[13];
    const float* b1    = (const float*)d_in[14];
    const float* W2    = (const float*)d_in[15];
    const float* b2    = (const float*)d_in[16];
    const float* lnf_g = (const float*)d_in[17];
    const float* lnf_b = (const float*)d_in[18];
    const float* Wlm   = (const float*)d_in[19];
    const float* blm   = (const float*)d_in[20];

    float *x, *logits_sym, *lossdummy;
    bf16 *hhi, *hlo, *qkvhi, *qkvlo, *ffhi, *fflo, *ohi, *olo, *wthi, *wtlo;
    cudaGetSymbolAddress((void**)&x,   g_x);
    cudaGetSymbolAddress((void**)&logits_sym, g_logits);
    cudaGetSymbolAddress((void**)&lossdummy,  g_lossdummy);
    cudaGetSymbolAddress((void**)&hhi, g_hhi);
    cudaGetSymbolAddress((void**)&hlo, g_hlo);
    cudaGetSymbolAddress((void**)&qkvhi, g_qkvhi);
    cudaGetSymbolAddress((void**)&qkvlo, g_qkvlo);
    cudaGetSymbolAddress((void**)&ffhi, g_ffhi);
    cudaGetSymbolAddress((void**)&fflo, g_fflo);
    cudaGetSymbolAddress((void**)&ohi, g_ohi);
    cudaGetSymbolAddress((void**)&olo, g_olo);
    cudaGetSymbolAddress((void**)&wthi, g_wthi);
    cudaGetSymbolAddress((void**)&wtlo, g_wtlo);

    cudaFuncSetAttribute(mma_gemm, cudaFuncAttributeMaxDynamicSharedMemorySize, GEMM_SMEM);
    cudaFuncSetAttribute(flash_attn, cudaFuncAttributeMaxDynamicSharedMemorySize, FL_SMEM);

    const long long BTV = (long long)BT_ * V_;
    float* out = (float*)d_out;
    float* logits = ((long long)out_size >= BTV) ? out : logits_sym;
    float* lossdst;
    if ((long long)out_size > BTV)       lossdst = out + BTV;
    else if ((long long)out_size < BTV)  lossdst = out;
    else                                 lossdst = lossdummy;

    embed_kernel<<<(BT_ * E_) / 256, 256>>>(context, tok_emb, pos_emb);

    dim3 gQKV(3 * E_ / 128, BT_ / 128);
    dim3 gE(E_ / 128, BT_ / 128);
    dim3 gFF(FF_ / 128, BT_ / 128);
    dim3 gV2(V_ / 128, BT_ / 128);
    dim3 gFL(B_ * H_, T_ / 128);
    dim3 gVT(T_ / 32, HD_ / 32, B_ * H_);
    dim3 tT(8, 32);
    dim3 tVT(32, 32);

    for (int l = 0; l < L_; l++) {
        const float* wq = Wq + (size_t)l * E_ * E_;
        const float* wk = Wk + (size_t)l * E_ * E_;
        const float* wv = Wv + (size_t)l * E_ * E_;
        const float* wo = Wo + (size_t)l * E_ * E_;
        const float* w1 = W1 + (size_t)l * E_ * FF_;
        const float* w2 = W2 + (size_t)l * FF_ * E_;

        // ---- attention block ----
        ln_split_kernel<<<BT_, 256>>>(x, hhi, hlo, ln1_g + l * E_, ln1_b + l * E_);
        wt_tsplit<<<dim3(E_ / 32, E_ / 32), tT>>>(wq, wthi,                       wtlo,                       E_, E_);
        wt_tsplit<<<dim3(E_ / 32, E_ / 32), tT>>>(wk, wthi + (size_t)E_ * E_,     wtlo + (size_t)E_ * E_,     E_, E_);
        wt_tsplit<<<dim3(E_ / 32, E_ / 32), tT>>>(wv, wthi + (size_t)2 * E_ * E_, wtlo + (size_t)2 * E_ * E_, E_, E_);
        mma_gemm<<<gQKV, 256, GEMM_SMEM>>>(hhi, hlo, E_, wthi, wtlo, E_,
                                           nullptr, nullptr, nullptr, qkvhi, qkvlo,
                                           3 * E_, E_, 0);
        vt_tsplit_kernel<<<gVT, tVT>>>();
        flash_attn<<<gFL, 256, FL_SMEM>>>();
        wt_tsplit<<<dim3(E_ / 32, E_ / 32), tT>>>(wo, wthi, wtlo, E_, E_);
        mma_gemm<<<gE, 256, GEMM_SMEM>>>(ohi, olo, E_, wthi, wtlo, E_,
                                         bo + l * E_, x, x, nullptr, nullptr,
                                         E_, E_, 0);

        // ---- MLP block ----
        ln_split_kernel<<<BT_, 256>>>(x, hhi, hlo, ln2_g + l * E_, ln2_b + l * E_);
        wt_tsplit<<<dim3(FF_ / 32, E_ / 32), tT>>>(w1, wthi, wtlo, FF_, E_);
        mma_gemm<<<gFF, 256, GEMM_SMEM>>>(hhi, hlo, E_, wthi, wtlo, E_,
                                          b1 + l * FF_, nullptr, nullptr, ffhi, fflo,
                                          FF_, E_, 1);
        wt_tsplit<<<dim3(E_ / 32, FF_ / 32), tT>>>(w2, wthi, wtlo, E_, FF_);
        mma_gemm<<<gE, 256, GEMM_SMEM>>>(ffhi, fflo, FF_, wthi, wtlo, FF_,
                                         b2 + l * E_, x, x, nullptr, nullptr,
                                         E_, FF_, 0);
    }

    // ---- final LN + LM head ----
    ln_split_kernel<<<BT_, 256>>>(x, hhi, hlo, lnf_g, lnf_b);
    wt_tsplit<<<dim3(V_ / 32, E_ / 32), tT>>>(Wlm, wthi, wtlo, V_, E_);
    mma_gemm<<<gV2, 256, GEMM_SMEM>>>(hhi, hlo, E_, wthi, wtlo, E_,
                                      blm, nullptr, logits, nullptr, nullptr,
                                      V_, E_, 0);

    rowloss_kernel<<<BT_, 256>>>(logits, targets);
    loss_final_kernel<<<1, 256>>>(lossdst);
}

// round 16
// speedup vs baseline: 1.4136x; 1.0957x over previous
#include <cuda_runtime.h>
#include <cuda_bf16.h>
#include <stdint.h>
#include <math.h>

// ---------------- problem constants ----------------
#define B_   2
#define T_   1024
#define E_   1024
#define H_   16
#define HD_  64
#define L_   8
#define FF_  4096
#define V_   32000
#define BT_  (B_ * T_)
#define EPS_ 1e-5f
#define SCALE_ 0.03125f   // 1/sqrt(E)

typedef __nv_bfloat16 bf16;

// ---------------- scratch (device globals) ----------------
__device__ float g_x[BT_ * E_];
__device__ float g_logits[(size_t)BT_ * V_];
__device__ float g_rowloss[BT_];
__device__ float g_lossdummy[4];
__device__ bf16 g_hhi[BT_ * E_];
__device__ bf16 g_hlo[BT_ * E_];
__device__ bf16 g_qkvhi[BT_ * 3 * E_];
__device__ bf16 g_qkvlo[BT_ * 3 * E_];
__device__ bf16 g_vthi[(size_t)B_ * H_ * HD_ * T_];
__device__ bf16 g_vtlo[(size_t)B_ * H_ * HD_ * T_];
__device__ bf16 g_ffhi[(size_t)BT_ * FF_];
__device__ bf16 g_fflo[(size_t)BT_ * FF_];
__device__ bf16 g_ohi[BT_ * E_];
__device__ bf16 g_olo[BT_ * E_];
__device__ bf16 g_wthi[(size_t)V_ * E_];
__device__ bf16 g_wtlo[(size_t)V_ * E_];

// single dynamic-shared symbol for all kernels
extern __shared__ bf16 smem[];

// ---------------- reductions (blockDim.x == 256) ----------------
__device__ __forceinline__ float blockSum256(float v) {
    __shared__ float sh[8];
    int tid = threadIdx.x;
    #pragma unroll
    for (int o = 16; o; o >>= 1) v += __shfl_xor_sync(0xffffffffu, v, o);
    __syncthreads();
    if ((tid & 31) == 0) sh[tid >> 5] = v;
    __syncthreads();
    v = sh[tid & 7];
    #pragma unroll
    for (int o = 4; o; o >>= 1) v += __shfl_xor_sync(0xffffffffu, v, o);
    return v;
}

__device__ __forceinline__ float blockMax256(float v) {
    __shared__ float sh[8];
    int tid = threadIdx.x;
    #pragma unroll
    for (int o = 16; o; o >>= 1) v = fmaxf(v, __shfl_xor_sync(0xffffffffu, v, o));
    __syncthreads();
    if ((tid & 31) == 0) sh[tid >> 5] = v;
    __syncthreads();
    v = sh[tid & 7];
    #pragma unroll
    for (int o = 4; o; o >>= 1) v = fmaxf(v, __shfl_xor_sync(0xffffffffu, v, o));
    return v;
}

// ---------------- embedding ----------------
__global__ void embed_kernel(const int* __restrict__ ctx,
                             const float* __restrict__ tok,
                             const float* __restrict__ pos) {
    int gid = blockIdx.x * blockDim.x + threadIdx.x;
    int bt = gid >> 10;
    int e  = gid & (E_ - 1);
    int t  = bt & (T_ - 1);
    g_x[gid] = tok[(size_t)ctx[bt] * E_ + e] + pos[t * E_ + e];
}

// ---------------- layernorm -> split bf16 hi/lo planes ----------------
__global__ void ln_split_kernel(const float* __restrict__ in,
                                bf16* __restrict__ hhi, bf16* __restrict__ hlo,
                                const float* __restrict__ g, const float* __restrict__ b) {
    int row = blockIdx.x;
    int tid = threadIdx.x;
    const float4* rp = (const float4*)(in + (size_t)row * E_);
    float4 v = rp[tid];
    float s  = v.x + v.y + v.z + v.w;
    float ss = v.x * v.x + v.y * v.y + v.z * v.z + v.w * v.w;
    s  = blockSum256(s);
    __syncthreads();
    ss = blockSum256(ss);
    float mean = s * (1.0f / E_);
    float var  = ss * (1.0f / E_) - mean * mean;
    float inv  = rsqrtf(var + EPS_);
    int e = tid * 4;
    float o[4];
    o[0] = (v.x - mean) * inv * g[e + 0] + b[e + 0];
    o[1] = (v.y - mean) * inv * g[e + 1] + b[e + 1];
    o[2] = (v.z - mean) * inv * g[e + 2] + b[e + 2];
    o[3] = (v.w - mean) * inv * g[e + 3] + b[e + 3];
    ushort4 ho, lw;
    unsigned short* hp = &ho.x;
    unsigned short* lp = &lw.x;
    #pragma unroll
    for (int j = 0; j < 4; j++) {
        bf16 h = __float2bfloat16(o[j]);
        bf16 l = __float2bfloat16(o[j] - __bfloat162float(h));
        hp[j] = __bfloat16_as_ushort(h);
        lp[j] = __bfloat16_as_ushort(l);
    }
    ((ushort4*)(hhi + (size_t)row * E_))[tid] = ho;
    ((ushort4*)(hlo + (size_t)row * E_))[tid] = lw;
}

// ---------------- weight transpose+split ----------------
__global__ void wt_tsplit(const float* __restrict__ W,
                          bf16* __restrict__ Thi, bf16* __restrict__ Tlo,
                          int N, int K) {
    __shared__ float s[32][33];
    int n0 = blockIdx.x * 32;
    int k0 = blockIdx.y * 32;
    int tx = threadIdx.x;   // 0..7
    int ty = threadIdx.y;   // 0..31
    float4 rv = *(const float4*)(W + (size_t)(k0 + ty) * N + n0 + tx * 4);
    s[ty][tx * 4 + 0] = rv.x;
    s[ty][tx * 4 + 1] = rv.y;
    s[ty][tx * 4 + 2] = rv.z;
    s[ty][tx * 4 + 3] = rv.w;
    __syncthreads();
    ushort4 ho, lw;
    unsigned short* hp = &ho.x;
    unsigned short* lp = &lw.x;
    #pragma unroll
    for (int j = 0; j < 4; j++) {
        float f = s[tx * 4 + j][ty];
        bf16 h = __float2bfloat16(f);
        bf16 l = __float2bfloat16(f - __bfloat162float(h));
        hp[j] = __bfloat16_as_ushort(h);
        lp[j] = __bfloat16_as_ushort(l);
    }
    size_t off = (size_t)(n0 + ty) * K + k0 + tx * 4;
    *(ushort4*)(Thi + off) = ho;
    *(ushort4*)(Tlo + off) = lw;
}

// ---------------- V transpose per head ----------------
__global__ void vt_tsplit_kernel() {
    __shared__ bf16 sh[32][33];
    __shared__ bf16 sl[32][33];
    int z = blockIdx.z;  int b = z >> 4;  int h = z & 15;
    int t0 = blockIdx.x * 32, d0 = blockIdx.y * 32;
    int tx = threadIdx.x, ty = threadIdx.y;
    size_t src = (size_t)(b * T_ + t0 + ty) * (3 * E_) + 2 * E_ + h * HD_ + d0 + tx;
    sh[ty][tx] = g_qkvhi[src];
    sl[ty][tx] = g_qkvlo[src];
    __syncthreads();
    size_t dst = (size_t)(z * HD_ + d0 + ty) * T_ + t0 + tx;
    g_vthi[dst] = sh[tx][ty];
    g_vtlo[dst] = sl[tx][ty];
}

// ============ MMA helpers ============
#define MMA16816(c, a, b) \
  asm volatile("mma.sync.aligned.m16n8k16.row.col.f32.bf16.bf16.f32 " \
    "{%0,%1,%2,%3}, {%4,%5,%6,%7}, {%8,%9}, {%0,%1,%2,%3};" \
    : "+f"((c)[0]), "+f"((c)[1]), "+f"((c)[2]), "+f"((c)[3]) \
    : "r"((a)[0]), "r"((a)[1]), "r"((a)[2]), "r"((a)[3]), \
      "r"((b)[0]), "r"((b)[1]))

#define CP16(dst_u32, src) \
  asm volatile("cp.async.cg.shared.global [%0], [%1], 16;" :: "r"(dst_u32), "l"(src))

__device__ __forceinline__ void ldsm4(uint32_t* r, unsigned a) {
    asm volatile("ldmatrix.sync.aligned.m8n8.x4.shared.b16 {%0,%1,%2,%3}, [%4];"
        : "=r"(r[0]), "=r"(r[1]), "=r"(r[2]), "=r"(r[3]) : "r"(a));
}

__device__ __forceinline__ void splitpack2(const float* v, uint32_t& hi, uint32_t& lo) {
    bf16 h0 = __float2bfloat16(v[0]);
    bf16 h1 = __float2bfloat16(v[1]);
    hi = (uint32_t)__bfloat16_as_ushort(h0) | ((uint32_t)__bfloat16_as_ushort(h1) << 16);
    bf16 l0 = __float2bfloat16(v[0] - __bfloat162float(h0));
    bf16 l1 = __float2bfloat16(v[1] - __bfloat162float(h1));
    lo = (uint32_t)__bfloat16_as_ushort(l0) | ((uint32_t)__bfloat16_as_ushort(l1) << 16);
}

#define SM_STAGE 20480
#define SM_MAT   5120
#define SM_ROW   40
#define SM_STAGE_B 40960u
#define SM_MAT_B   10240u
#define SM_TILE_B  1280u

// ============ bf16x3 GEMM, 128x128x32, 2-stage cp.async, 2 CTAs/SM ============
__global__ void __launch_bounds__(256, 2) mma_gemm(
        const bf16* __restrict__ Ahi, const bf16* __restrict__ Alo, int lda,
        const bf16* __restrict__ Bthi, const bf16* __restrict__ Btlo, int ldb,
        const float* __restrict__ bias, const float* __restrict__ res,
        float* __restrict__ C, bf16* __restrict__ Chi, bf16* __restrict__ Clo,
        int ldc, int K, int doRelu) {
    int tid  = threadIdx.x;
    int warp = tid >> 5, lane = tid & 31;
    int wm = warp & 3;
    int wn = warp >> 2;
    int g  = lane >> 2;
    int tg = lane & 3;
    int t  = lane >> 3, rr = lane & 7;

    int row0 = blockIdx.y * 128;
    int col0 = blockIdx.x * 128;

    const bf16* planes[4] = {Ahi, Alo, Bthi, Btlo};
    int lds[4] = {lda, lda, ldb, ldb};
    unsigned smem_u32 = (unsigned)__cvta_generic_to_shared(smem);

    unsigned aoffB = 2u * ((wm * 32 + (t & 1) * 8 + rr) * SM_ROW + (t >> 1) * 8);
    unsigned boffB = 2u * ((wn * 64 + (t >> 1) * 8 + rr) * SM_ROW + (t & 1) * 8);

    float acc[2][8][4];
    #pragma unroll
    for (int i = 0; i < 2; i++)
        #pragma unroll
        for (int j = 0; j < 8; j++)
            #pragma unroll
            for (int r = 0; r < 4; r++) acc[i][j][r] = 0.0f;

    int nk = K >> 5;

    auto load_stage = [&](int stage, int k0) {
        #pragma unroll
        for (int m = 0; m < 4; m++) {
            const bf16* P = planes[m];
            int base_row = (m < 2) ? row0 : col0;
            int ld = lds[m];
            #pragma unroll
            for (int rep = 0; rep < 2; rep++) {
                int chunk = rep * 256 + tid;
                int row = chunk >> 2;
                int kc  = chunk & 3;
                unsigned dst = smem_u32 +
                    2u * (stage * SM_STAGE + m * SM_MAT + row * SM_ROW + kc * 8);
                const bf16* src = P + (size_t)(base_row + row) * ld + k0 + kc * 8;
                CP16(dst, src);
            }
        }
        asm volatile("cp.async.commit_group;");
    };

    load_stage(0, 0);

    for (int kt = 0; kt < nk; kt++) {
        if (kt + 1 < nk) {
            load_stage((kt + 1) & 1, (kt + 1) << 5);
            asm volatile("cp.async.wait_group 1;");
        } else {
            asm volatile("cp.async.wait_group 0;");
        }
        __syncthreads();

        unsigned sb  = smem_u32 + (unsigned)(kt & 1) * SM_STAGE_B;
        unsigned aHi = sb + aoffB;
        unsigned aLo = aHi + SM_MAT_B;
        unsigned bHi = sb + 2u * SM_MAT_B + boffB;
        unsigned bLo = bHi + SM_MAT_B;

        #pragma unroll
        for (int kk = 0; kk < 32; kk += 16) {
            uint32_t ah[2][4], al[2][4];
            ldsm4(ah[0], aHi + 2 * kk);
            ldsm4(ah[1], aHi + SM_TILE_B + 2 * kk);
            ldsm4(al[0], aLo + 2 * kk);
            ldsm4(al[1], aLo + SM_TILE_B + 2 * kk);
            uint32_t bh[4][4], bl[4][4];
            #pragma unroll
            for (int p = 0; p < 4; p++) {
                ldsm4(bh[p], bHi + p * SM_TILE_B + 2 * kk);
                ldsm4(bl[p], bLo + p * SM_TILE_B + 2 * kk);
            }
            #pragma unroll
            for (int p = 0; p < 4; p++)
                #pragma unroll
                for (int mi = 0; mi < 2; mi++) {
                    MMA16816(acc[mi][2 * p],     ah[mi], &bh[p][0]);
                    MMA16816(acc[mi][2 * p + 1], ah[mi], &bh[p][2]);
                }
            #pragma unroll
            for (int p = 0; p < 4; p++)
                #pragma unroll
                for (int mi = 0; mi < 2; mi++) {
                    MMA16816(acc[mi][2 * p],     ah[mi], &bl[p][0]);
                    MMA16816(acc[mi][2 * p + 1], ah[mi], &bl[p][2]);
                }
            #pragma unroll
            for (int p = 0; p < 4; p++)
                #pragma unroll
                for (int mi = 0; mi < 2; mi++) {
                    MMA16816(acc[mi][2 * p],     al[mi], &bh[p][0]);
                    MMA16816(acc[mi][2 * p + 1], al[mi], &bh[p][2]);
                }
        }
        __syncthreads();
    }

    // ---- epilogue ----
    #pragma unroll
    for (int mi = 0; mi < 2; mi++) {
        int r = row0 + wm * 32 + mi * 16 + g;
        #pragma unroll
        for (int ni = 0; ni < 8; ni++) {
            int c = col0 + wn * 64 + ni * 8 + tg * 2;
            float v0 = acc[mi][ni][0], v1 = acc[mi][ni][1];
            float v2 = acc[mi][ni][2], v3 = acc[mi][ni][3];
            if (bias) {
                float b0 = bias[c], b1 = bias[c + 1];
                v0 += b0; v1 += b1; v2 += b0; v3 += b1;
            }
            if (doRelu) {
                v0 = fmaxf(v0, 0.0f); v1 = fmaxf(v1, 0.0f);
                v2 = fmaxf(v2, 0.0f); v3 = fmaxf(v3, 0.0f);
            }
            if (Chi) {
                float vv0[2] = {v0, v1}, vv1[2] = {v2, v3};
                uint32_t h0, l0, h1, l1;
                splitpack2(vv0, h0, l0);
                splitpack2(vv1, h1, l1);
                *(uint32_t*)(Chi + (size_t)r * ldc + c)       = h0;
                *(uint32_t*)(Chi + (size_t)(r + 8) * ldc + c) = h1;
                *(uint32_t*)(Clo + (size_t)r * ldc + c)       = l0;
                *(uint32_t*)(Clo + (size_t)(r + 8) * ldc + c) = l1;
            } else {
                if (res) {
                    v0 += res[(size_t)r * ldc + c];
                    v1 += res[(size_t)r * ldc + c + 1];
                    v2 += res[(size_t)(r + 8) * ldc + c];
                    v3 += res[(size_t)(r + 8) * ldc + c + 1];
                }
                *(float2*)(C + (size_t)r * ldc + c)       = make_float2(v0, v1);
                *(float2*)(C + (size_t)(r + 8) * ldc + c) = make_float2(v2, v3);
            }
        }
    }
}

// ============ fused flash attention (causal, bf16x3, online softmax) ============
#define FQ_ROW   72
#define FQ_PLANE (128 * FQ_ROW)
#define FV_ROW   136
#define FV_PLANE (64 * FV_ROW)
#define FK_BASE  (2 * FQ_PLANE)
#define FV_BASE  (FK_BASE + 4 * FQ_PLANE)
#define FRED_OFF (FV_BASE + 4 * FV_PLANE)
#define FL_SMEM  (FRED_OFF * 2 + 4 * 128 * 4)

__global__ void __launch_bounds__(256, 1) flash_attn() {
    int z = blockIdx.x;
    int qt = 7 - blockIdx.y;
    int b = z >> 4, h = z & 15;
    int tid = threadIdx.x, warp = tid >> 5, lane = tid & 31;
    int wm = warp & 3, wn = warp >> 2;
    int g = lane >> 2, tg = lane & 3;
    int t = lane >> 3, rr = lane & 7;
    int row0 = qt * 128;

    unsigned sb = (unsigned)__cvta_generic_to_shared(smem);
    float* rmax = (float*)(smem + FRED_OFF);
    float* rsum = rmax + 256;

    const bf16* Qh = g_qkvhi + (size_t)b * T_ * 3 * E_ + h * HD_;
    const bf16* Ql = g_qkvlo + (size_t)b * T_ * 3 * E_ + h * HD_;
    const bf16* Kh = Qh + E_;
    const bf16* Kl = Ql + E_;
    const bf16* Vh = g_vthi + (size_t)z * HD_ * T_;
    const bf16* Vl = g_vtlo + (size_t)z * HD_ * T_;

    #pragma unroll
    for (int i = 0; i < 8; i++) {
        int idx = i * 256 + tid;
        int plane = idx >> 10;
        int rem = idx & 1023;
        int r = rem >> 3, c = rem & 7;
        unsigned dst = sb + 2u * ((unsigned)plane * FQ_PLANE + r * FQ_ROW + c * 8);
        const bf16* P = plane ? Ql : Qh;
        CP16(dst, P + (size_t)(row0 + r) * (3 * E_) + c * 8);
    }
    auto load_kv = [&](int stage, int kt) {
        #pragma unroll
        for (int i = 0; i < 8; i++) {
            int idx = i * 256 + tid;
            int plane = idx >> 10;
            int rem = idx & 1023;
            int r = rem >> 3, c = rem & 7;
            unsigned dst = sb + 2u * ((unsigned)(FK_BASE + stage * 2 * FQ_PLANE)
                                      + (unsigned)plane * FQ_PLANE + r * FQ_ROW + c * 8);
            const bf16* P = plane ? Kl : Kh;
            CP16(dst, P + (size_t)(kt * 128 + r) * (3 * E_) + c * 8);
        }
        #pragma unroll
        for (int i = 0; i < 8; i++) {
            int idx = i * 256 + tid;
            int plane = idx >> 10;
            int rem = idx & 1023;
            int r = rem >> 4, c = rem & 15;
            unsigned dst = sb + 2u * ((unsigned)(FV_BASE + stage * 2 * FV_PLANE)
                                      + (unsigned)plane * FV_PLANE + r * FV_ROW + c * 8);
            const bf16* P = plane ? Vl : Vh;
            CP16(dst, P + (size_t)r * T_ + kt * 128 + c * 8);
        }
        asm volatile("cp.async.commit_group;");
    };
    load_kv(0, 0);

    unsigned aoffB = 2u * ((wm * 32 + (t & 1) * 8 + rr) * FQ_ROW + (t >> 1) * 8);
    unsigned boffB = 2u * ((wn * 64 + (t >> 1) * 8 + rr) * FQ_ROW + (t & 1) * 8);
    unsigned voffB = 2u * (((t >> 1) * 8 + rr) * FV_ROW + (t & 1) * 8);

    float acc_o[2][8][4];
    #pragma unroll
    for (int i = 0; i < 2; i++)
        #pragma unroll
        for (int j = 0; j < 8; j++)
            #pragma unroll
            for (int r = 0; r < 4; r++) acc_o[i][j][r] = 0.0f;
    float m_run[2][2] = {{-1e30f, -1e30f}, {-1e30f, -1e30f}};
    float l_run[2][2] = {{0.0f, 0.0f}, {0.0f, 0.0f}};

    int myrow[2][2];
    #pragma unroll
    for (int mi = 0; mi < 2; mi++)
        #pragma unroll
        for (int hh = 0; hh < 2; hh++)
            myrow[mi][hh] = wm * 32 + mi * 16 + g + hh * 8;

    for (int kt = 0; kt <= qt; kt++) {
        if (kt + 1 <= qt) load_kv((kt + 1) & 1, kt + 1);
        if (kt + 1 <= qt) { asm volatile("cp.async.wait_group 1;"); }
        else              { asm volatile("cp.async.wait_group 0;"); }
        __syncthreads();

        float acc_s[2][8][4];
        #pragma unroll
        for (int i = 0; i < 2; i++)
            #pragma unroll
            for (int j = 0; j < 8; j++)
                #pragma unroll
                for (int r = 0; r < 4; r++) acc_s[i][j][r] = 0.0f;

        unsigned qHi = sb + aoffB;
        unsigned qLo = qHi + 2u * FQ_PLANE;
        unsigned kHi = sb + 2u * (FK_BASE + (unsigned)(kt & 1) * 2 * FQ_PLANE) + boffB;
        unsigned kLo = kHi + 2u * FQ_PLANE;

        #pragma unroll
        for (int kk = 0; kk < 64; kk += 16) {
            uint32_t ah[2][4], al[2][4];
            ldsm4(ah[0], qHi + 2 * kk);
            ldsm4(ah[1], qHi + 16 * FQ_ROW * 2 + 2 * kk);
            ldsm4(al[0], qLo + 2 * kk);
            ldsm4(al[1], qLo + 16 * FQ_ROW * 2 + 2 * kk);
            uint32_t bh[4][4], bl[4][4];
            #pragma unroll
            for (int p = 0; p < 4; p++) {
                ldsm4(bh[p], kHi + p * (16 * FQ_ROW * 2) + 2 * kk);
                ldsm4(bl[p], kLo + p * (16 * FQ_ROW * 2) + 2 * kk);
            }
            #pragma unroll
            for (int p = 0; p < 4; p++)
                #pragma unroll
                for (int mi = 0; mi < 2; mi++) {
                    MMA16816(acc_s[mi][2 * p],     ah[mi], &bh[p][0]);
                    MMA16816(acc_s[mi][2 * p + 1], ah[mi], &bh[p][2]);
                }
            #pragma unroll
            for (int p = 0; p < 4; p++)
                #pragma unroll
                for (int mi = 0; mi < 2; mi++) {
                    MMA16816(acc_s[mi][2 * p],     ah[mi], &bl[p][0]);
                    MMA16816(acc_s[mi][2 * p + 1], ah[mi], &bl[p][2]);
                }
            #pragma unroll
            for (int p = 0; p < 4; p++)
                #pragma unroll
                for (int mi = 0; mi < 2; mi++) {
                    MMA16816(acc_s[mi][2 * p],     al[mi], &bh[p][0]);
                    MMA16816(acc_s[mi][2 * p + 1], al[mi], &bh[p][2]);
                }
        }

        if (kt == qt) {
            #pragma unroll
            for (int mi = 0; mi < 2; mi++)
                #pragma unroll
                for (int ni = 0; ni < 8; ni++)
                    #pragma unroll
                    for (int j = 0; j < 4; j++) {
                        int col = wn * 64 + ni * 8 + tg * 2 + (j & 1);
                        int rw  = myrow[mi][j >> 1];
                        acc_s[mi][ni][j] = (col > rw) ? -1e30f
                                          : acc_s[mi][ni][j] * SCALE_;
                    }
        } else {
            #pragma unroll
            for (int mi = 0; mi < 2; mi++)
                #pragma unroll
                for (int ni = 0; ni < 8; ni++)
                    #pragma unroll
                    for (int j = 0; j < 4; j++)
                        acc_s[mi][ni][j] *= SCALE_;
        }

        float lm[2][2] = {{-1e30f, -1e30f}, {-1e30f, -1e30f}};
        #pragma unroll
        for (int mi = 0; mi < 2; mi++)
            #pragma unroll
            for (int ni = 0; ni < 8; ni++)
                #pragma unroll
                for (int j = 0; j < 4; j++)
                    lm[mi][j >> 1] = fmaxf(lm[mi][j >> 1], acc_s[mi][ni][j]);
        #pragma unroll
        for (int mi = 0; mi < 2; mi++)
            #pragma unroll
            for (int hh = 0; hh < 2; hh++) {
                float v = lm[mi][hh];
                v = fmaxf(v, __shfl_xor_sync(0xffffffffu, v, 1));
                v = fmaxf(v, __shfl_xor_sync(0xffffffffu, v, 2));
                lm[mi][hh] = v;
                if (tg == 0) rmax[wn * 128 + myrow[mi][hh]] = v;
            }
        __syncthreads();
        float m_new[2][2], factor[2][2];
        #pragma unroll
        for (int mi = 0; mi < 2; mi++)
            #pragma unroll
            for (int hh = 0; hh < 2; hh++) {
                float tm = fmaxf(rmax[myrow[mi][hh]], rmax[128 + myrow[mi][hh]]);
                m_new[mi][hh] = fmaxf(m_run[mi][hh], tm);
                factor[mi][hh] = __expf(m_run[mi][hh] - m_new[mi][hh]);
            }

        float ls[2][2] = {{0.0f, 0.0f}, {0.0f, 0.0f}};
        #pragma unroll
        for (int mi = 0; mi < 2; mi++)
            #pragma unroll
            for (int ni = 0; ni < 8; ni++)
                #pragma unroll
                for (int j = 0; j < 4; j++) {
                    float e = __expf(acc_s[mi][ni][j] - m_new[mi][j >> 1]);
                    acc_s[mi][ni][j] = e;
                    ls[mi][j >> 1] += e;
                }
        #pragma unroll
        for (int mi = 0; mi < 2; mi++)
            #pragma unroll
            for (int hh = 0; hh < 2; hh++) {
                float v = ls[mi][hh];
                v += __shfl_xor_sync(0xffffffffu, v, 1);
                v += __shfl_xor_sync(0xffffffffu, v, 2);
                ls[mi][hh] = v;
                if (tg == 0) rsum[wn * 128 + myrow[mi][hh]] = v;
            }
        __syncthreads();
        #pragma unroll
        for (int mi = 0; mi < 2; mi++)
            #pragma unroll
            for (int hh = 0; hh < 2; hh++) {
                float srow = rsum[myrow[mi][hh]] + rsum[128 + myrow[mi][hh]];
                l_run[mi][hh] = l_run[mi][hh] * factor[mi][hh] + srow;
                m_run[mi][hh] = m_new[mi][hh];
            }

        #pragma unroll
        for (int mi = 0; mi < 2; mi++)
            #pragma unroll
            for (int no = 0; no < 8; no++)
                #pragma unroll
                for (int j = 0; j < 4; j++)
                    acc_o[mi][no][j] *= factor[mi][j >> 1];

        unsigned vHiB = sb + 2u * (FV_BASE + (unsigned)(kt & 1) * 2 * FV_PLANE) + voffB;
        unsigned vLoB = vHiB + 2u * FV_PLANE;
        #pragma unroll
        for (int p = 0; p < 4; p++) {
            uint32_t ph[2][4], pl[2][4];
            #pragma unroll
            for (int mi = 0; mi < 2; mi++) {
                splitpack2(&acc_s[mi][2 * p][0],     ph[mi][0], pl[mi][0]);
                splitpack2(&acc_s[mi][2 * p][2],     ph[mi][1], pl[mi][1]);
                splitpack2(&acc_s[mi][2 * p + 1][0], ph[mi][2], pl[mi][2]);
                splitpack2(&acc_s[mi][2 * p + 1][2], ph[mi][3], pl[mi][3]);
            }
            unsigned kcol = 2u * (wn * 64 + p * 16);
            #pragma unroll
            for (int po = 0; po < 4; po++) {
                uint32_t bh[4], bl[4];
                ldsm4(bh, vHiB + po * (16 * FV_ROW * 2) + kcol);
                ldsm4(bl, vLoB + po * (16 * FV_ROW * 2) + kcol);
                #pragma unroll
                for (int mi = 0; mi < 2; mi++) {
                    MMA16816(acc_o[mi][2 * po],     ph[mi], &bh[0]);
                    MMA16816(acc_o[mi][2 * po + 1], ph[mi], &bh[2]);
                    MMA16816(acc_o[mi][2 * po],     ph[mi], &bl[0]);
                    MMA16816(acc_o[mi][2 * po + 1], ph[mi], &bl[2]);
                    MMA16816(acc_o[mi][2 * po],     pl[mi], &bh[0]);
                    MMA16816(acc_o[mi][2 * po + 1], pl[mi], &bh[2]);
                }
            }
        }
        __syncthreads();
    }

    float* osh = (float*)smem;
    __syncthreads();
    if (wn == 1) {
        #pragma unroll
        for (int mi = 0; mi < 2; mi++)
            #pragma unroll
            for (int no = 0; no < 8; no++)
                #pragma unroll
                for (int j = 0; j < 4; j++) {
                    int rw = myrow[mi][j >> 1];
                    int cl = no * 8 + tg * 2 + (j & 1);
                    osh[rw * 64 + cl] = acc_o[mi][no][j];
                }
    }
    __syncthreads();
    if (wn == 0) {
        #pragma unroll
        for (int mi = 0; mi < 2; mi++)
            #pragma unroll
            for (int hh = 0; hh < 2; hh++) {
                float invl = 1.0f / l_run[mi][hh];
                int rw = myrow[mi][hh];
                int rglob = b * T_ + row0 + rw;
                #pragma unroll
                for (int no = 0; no < 8; no++) {
                    int cl = no * 8 + tg * 2;
                    float vv[2];
                    vv[0] = (acc_o[mi][no][hh * 2 + 0] + osh[rw * 64 + cl])     * invl;
                    vv[1] = (acc_o[mi][no][hh * 2 + 1] + osh[rw * 64 + cl + 1]) * invl;
                    uint32_t hi, lo;
                    splitpack2(vv, hi, lo);
                    *(uint32_t*)(g_ohi + (size_t)rglob * E_ + h * HD_ + cl) = hi;
                    *(uint32_t*)(g_olo + (size_t)rglob * E_ + h * HD_ + cl) = lo;
                }
            }
    }
}

// ---------------- loss ----------------
__global__ void rowloss_kernel(const float* __restrict__ logits, const int* __restrict__ tgt) {
    int row = blockIdx.x;
    const float* lr = logits + (size_t)row * V_;
    int tid = threadIdx.x;
    float m = -1e30f;
    for (int i = tid; i < V_; i += 256) m = fmaxf(m, lr[i]);
    m = blockMax256(m);
    __syncthreads();
    float s = 0.0f;
    for (int i = tid; i < V_; i += 256) s += __expf(lr[i] - m);
    s = blockSum256(s);
    if (tid == 0)
        g_rowloss[row] = -(lr[tgt[row]] - m - logf(s));
}

__global__ void loss_final_kernel(float* __restrict__ dst) {
    int tid = threadIdx.x;
    float s = 0.0f;
    for (int i = tid; i < BT_; i += 256) s += g_rowloss[i];
    s = blockSum256(s);
    if (tid == 0) dst[0] = s * (1.0f / BT_);
}

// ---------------- host driver ----------------
#define GEMM_SMEM 81920

extern "C" void kernel_launch(void* const* d_in, const int* in_sizes, int n_in,
                              void* d_out, int out_size) {
    const int*   context = (const int*)  d_in[0];
    const int*   targets = (const int*)  d_in[1];
    const float* tok_emb = (const float*)d_in[2];
    const float* pos_emb = (const float*)d_in[3];
    const float* Wq    = (const float*)d_in[4];
    const float* Wk    = (const float*)d_in[5];
    const float* Wv    = (const float*)d_in[6];
    const float* Wo    = (const float*)d_in[7];
    const float* bo    = (const float*)d_in[8];
    const float* ln1_g = (const float*)d_in[9];
    const float* ln1_b = (const float*)d_in[10];
    const float* ln2_g = (const float*)d_in[11];
    const float* ln2_b = (const float*)d_in[12];
    const float* W1    = (const float*)d_in[13];
    const float* b1    = (const float*)d_in[14];
    const float* W2    = (const float*)d_in[15];
    const float* b2    = (const float*)d_in[16];
    const float* lnf_g = (const float*)d_in[17];
    const float* lnf_b = (const float*)d_in[18];
    const float* Wlm   = (const float*)d_in[19];
    const float* blm   = (const float*)d_in[20];

    float *x, *logits_sym, *lossdummy;
    bf16 *hhi, *hlo, *qkvhi, *qkvlo, *ffhi, *fflo, *ohi, *olo, *wthi, *wtlo;
    cudaGetSymbolAddress((void**)&x,   g_x);
    cudaGetSymbolAddress((void**)&logits_sym, g_logits);
    cudaGetSymbolAddress((void**)&lossdummy,  g_lossdummy);
    cudaGetSymbolAddress((void**)&hhi, g_hhi);
    cudaGetSymbolAddress((void**)&hlo, g_hlo);
    cudaGetSymbolAddress((void**)&qkvhi, g_qkvhi);
    cudaGetSymbolAddress((void**)&qkvlo, g_qkvlo);
    cudaGetSymbolAddress((void**)&ffhi, g_ffhi);
    cudaGetSymbolAddress((void**)&fflo, g_fflo);
    cudaGetSymbolAddress((void**)&ohi, g_ohi);
    cudaGetSymbolAddress((void**)&olo, g_olo);
    cudaGetSymbolAddress((void**)&wthi, g_wthi);
    cudaGetSymbolAddress((void**)&wtlo, g_wtlo);

    cudaFuncSetAttribute(mma_gemm, cudaFuncAttributeMaxDynamicSharedMemorySize, GEMM_SMEM);
    cudaFuncSetAttribute(flash_attn, cudaFuncAttributeMaxDynamicSharedMemorySize, FL_SMEM);

    const long long BTV = (long long)BT_ * V_;
    float* out = (float*)d_out;
    float* logits = ((long long)out_size >= BTV) ? out : logits_sym;
    float* lossdst;
    if ((long long)out_size > BTV)       lossdst = out + BTV;
    else if ((long long)out_size < BTV)  lossdst = out;
    else                                 lossdst = lossdummy;

    embed_kernel<<<(BT_ * E_) / 256, 256>>>(context, tok_emb, pos_emb);

    dim3 gQKV(3 * E_ / 128, BT_ / 128);
    dim3 gE(E_ / 128, BT_ / 128);
    dim3 gFF(FF_ / 128, BT_ / 128);
    dim3 gV2(V_ / 128, BT_ / 128);
    dim3 gFL(B_ * H_, T_ / 128);
    dim3 gVT(T_ / 32, HD_ / 32, B_ * H_);
    dim3 tT(8, 32);
    dim3 tVT(32, 32);

    for (int l = 0; l < L_; l++) {
        const float* wq = Wq + (size_t)l * E_ * E_;
        const float* wk = Wk + (size_t)l * E_ * E_;
        const float* wv = Wv + (size_t)l * E_ * E_;
        const float* wo = Wo + (size_t)l * E_ * E_;
        const float* w1 = W1 + (size_t)l * E_ * FF_;
        const float* w2 = W2 + (size_t)l * FF_ * E_;

        // ---- attention block ----
        ln_split_kernel<<<BT_, 256>>>(x, hhi, hlo, ln1_g + l * E_, ln1_b + l * E_);
        wt_tsplit<<<dim3(E_ / 32, E_ / 32), tT>>>(wq, wthi,                       wtlo,                       E_, E_);
        wt_tsplit<<<dim3(E_ / 32, E_ / 32), tT>>>(wk, wthi + (size_t)E_ * E_,     wtlo + (size_t)E_ * E_,     E_, E_);
        wt_tsplit<<<dim3(E_ / 32, E_ / 32), tT>>>(wv, wthi + (size_t)2 * E_ * E_, wtlo + (size_t)2 * E_ * E_, E_, E_);
        mma_gemm<<<gQKV, 256, GEMM_SMEM>>>(hhi, hlo, E_, wthi, wtlo, E_,
                                           nullptr, nullptr, nullptr, qkvhi, qkvlo,
                                           3 * E_, E_, 0);
        vt_tsplit_kernel<<<gVT, tVT>>>();
        flash_attn<<<gFL, 256, FL_SMEM>>>();
        wt_tsplit<<<dim3(E_ / 32, E_ / 32), tT>>>(wo, wthi, wtlo, E_, E_);
        mma_gemm<<<gE, 256, GEMM_SMEM>>>(ohi, olo, E_, wthi, wtlo, E_,
                                         bo + l * E_, x, x, nullptr, nullptr,
                                         E_, E_, 0);

        // ---- MLP block ----
        ln_split_kernel<<<BT_, 256>>>(x, hhi, hlo, ln2_g + l * E_, ln2_b + l * E_);
        wt_tsplit<<<dim3(FF_ / 32, E_ / 32), tT>>>(w1, wthi, wtlo, FF_, E_);
        mma_gemm<<<gFF, 256, GEMM_SMEM>>>(hhi, hlo, E_, wthi, wtlo, E_,
                                          b1 + l * FF_, nullptr, nullptr, ffhi, fflo,
                                          FF_, E_, 1);
        wt_tsplit<<<dim3(E_ / 32, FF_ / 32), tT>>>(w2, wthi, wtlo, E_, FF_);
        mma_gemm<<<gE, 256, GEMM_SMEM>>>(ffhi, fflo, FF_, wthi, wtlo, FF_,
                                         b2 + l * E_, x, x, nullptr, nullptr,
                                         E_, FF_, 0);
    }

    // ---- final LN + LM head ----
    ln_split_kernel<<<BT_, 256>>>(x, hhi, hlo, lnf_g, lnf_b);
    wt_tsplit<<<dim3(V_ / 32, E_ / 32), tT>>>(Wlm, wthi, wtlo, V_, E_);
    mma_gemm<<<gV2, 256, GEMM_SMEM>>>(hhi, hlo, E_, wthi, wtlo, E_,
                                      blm, nullptr, logits, nullptr, nullptr,
                                      V_, E_, 0);

    rowloss_kernel<<<BT_, 256>>>(logits, targets);
    loss_final_kernel<<<1, 256>>>(lossdst);
}